// round 10
// baseline (speedup 1.0000x reference)
#include <cuda_runtime.h>
#include <math.h>
#include <stdint.h>

#define Bc 2
#define Tc 1024
#define Cc 1024
#define Hc 16
#define Dc 64
#define Ec 16
#define Ic 256
#define Nc (Bc*Tc)

typedef unsigned long long ull;

__device__ float g_h  [Nc*Cc];
__device__ float g_q  [Nc*Cc];
__device__ float g_k  [Nc*Cc];
__device__ float g_v  [Nc*Cc];
__device__ float g_ao [Nc*Cc];
__device__ float g_x1 [Nc*Cc];
__device__ float g_mid[(long long)Ec*Nc*Ic];
__device__ float g_w1t[(long long)Ec*Ic*Cc];
__device__ float g_w2t[(long long)Ec*Cc*Ic];
__device__ float g_eo_scr[(long long)Nc*Ec*Cc];
__device__ float g_mask[Nc*Ec];
__device__ float g_colinv[Ec];
__device__ float g_scores_scr[Nc*Ec];
__device__ float g_kpt_scr[Nc];
__device__ int   g_cnt[Ec];
__device__ int   g_idx[Ec*Nc];

__device__ __forceinline__ float gelu_f(float x) {
    return 0.5f * x * (1.0f + erff(x * 0.70710678118654752440f));
}
__device__ __forceinline__ uint32_t smem_u32(const void* p) {
    uint32_t a;
    asm("{ .reg .u64 t; cvta.to.shared.u64 t, %1; cvt.u32.u64 %0, t; }" : "=r"(a) : "l"(p));
    return a;
}
__device__ __forceinline__ float tf32r(float x) {
    float o; asm("cvt.rna.tf32.f32 %0, %1;" : "=f"(o) : "f"(x)); return o;
}
__device__ __forceinline__ void sts128(uint32_t a, float4 v) {
    asm volatile("st.shared.v4.b32 [%0], {%1,%2,%3,%4};" ::
                 "r"(a), "f"(v.x), "f"(v.y), "f"(v.z), "f"(v.w) : "memory");
}
__device__ __forceinline__ void ldsm4(uint32_t (&d)[4], uint32_t addr) {
    asm volatile("ldmatrix.sync.aligned.m8n8.x4.shared.b16 {%0,%1,%2,%3}, [%4];"
                 : "=r"(d[0]), "=r"(d[1]), "=r"(d[2]), "=r"(d[3]) : "r"(addr));
}
__device__ __forceinline__ void mma_tf32(float (&c)[4], const uint32_t (&a)[4], const uint32_t* b) {
    asm volatile("mma.sync.aligned.m16n8k8.row.col.f32.tf32.tf32.f32 "
                 "{%0,%1,%2,%3}, {%4,%5,%6,%7}, {%8,%9}, {%0,%1,%2,%3};"
                 : "+f"(c[0]), "+f"(c[1]), "+f"(c[2]), "+f"(c[3])
                 : "r"(a[0]), "r"(a[1]), "r"(a[2]), "r"(a[3]), "r"(b[0]), "r"(b[1]));
}
__device__ __forceinline__ ull dup2(float x) {
    ull r; asm("mov.b64 %0, {%1,%1};" : "=l"(r) : "f"(x)); return r;
}
__device__ __forceinline__ void fma2(ull &c, ull a, ull b) {
    asm("fma.rn.f32x2 %0, %1, %2, %0;" : "+l"(c) : "l"(a), "l"(b));
}
__device__ __forceinline__ ull mul2(ull a, ull b) {
    ull d; asm("mul.rn.f32x2 %0, %1, %2;" : "=l"(d) : "l"(a), "l"(b)); return d;
}
__device__ __forceinline__ float2 unpk(ull v) {
    float2 f; asm("mov.b64 {%0,%1}, %2;" : "=f"(f.x), "=f"(f.y) : "l"(v)); return f;
}

// ================= MoE tf32 MMA (gathered / scattered, expert-offset batched) =================
#define MOE_SMEM 65536

__global__ void __launch_bounds__(256) moe_g1_k(
    const float* __restrict__ A, const float* __restrict__ B, float* __restrict__ C,
    const int* __restrict__ idxp, const int* __restrict__ cntp, int e0)
{
    extern __shared__ float dsm[];
    const int e = e0 + blockIdx.z, tm = blockIdx.y, tn = blockIdx.x;
    const int ce = cntp[e];
    if ((tm << 7) >= ce) return;
    const int tid = threadIdx.x, wid = tid >> 5, lane = tid & 31;
    const int warpM = wid >> 2, warpN = wid & 3;
    const uint32_t sbase = smem_u32(dsm);

    int srcA[4];
    #pragma unroll
    for (int k = 0; k < 4; k++) {
        const int r = (tid + (k << 8)) >> 3;
        int gr = (tm << 7) + r;
        if (gr >= ce) gr = ce - 1;
        srcA[k] = idxp[e * Nc + gr];
    }
    const float* Bt = B + (long long)e * ((long long)Ic * Cc) + ((long long)tn << 7) * Cc;

    float acc[4][4][4];
    #pragma unroll
    for (int i = 0; i < 4; i++)
        #pragma unroll
        for (int j = 0; j < 4; j++)
            #pragma unroll
            for (int r = 0; r < 4; r++) acc[i][j][r] = 0.f;

    auto ldst = [&](int s, int k0) {
        const uint32_t ab = sbase + (uint32_t)s * 32768u;
        const uint32_t bb = ab + 16384u;
        #pragma unroll
        for (int k = 0; k < 4; k++) {
            const int u = tid + (k << 8), r = u >> 3, c = u & 7;
            float4 v = *(const float4*)(A + (long long)srcA[k] * Cc + k0 + (c << 2));
            v = make_float4(tf32r(v.x), tf32r(v.y), tf32r(v.z), tf32r(v.w));
            sts128(ab + ((uint32_t)r << 7) + ((uint32_t)(c ^ (r & 7)) << 4), v);
        }
        #pragma unroll
        for (int k = 0; k < 4; k++) {
            const int u = tid + (k << 8), r = u >> 3, c = u & 7;
            float4 v = *(const float4*)(Bt + (long long)r * Cc + k0 + (c << 2));
            v = make_float4(tf32r(v.x), tf32r(v.y), tf32r(v.z), tf32r(v.w));
            sts128(bb + ((uint32_t)r << 7) + ((uint32_t)(c ^ (r & 7)) << 4), v);
        }
    };

    const int rA = warpM * 64 + ((lane & 8) ? 8 : 0) + (lane & 7);
    const int chA = lane >> 4;
    const int rB = warpN * 32 + ((lane >> 4) << 3) + (lane & 7);
    const int chB = (lane >> 3) & 1;

    ldst(0, 0);
    __syncthreads();
    for (int kc = 0; kc < 32; kc++) {
        if (kc + 1 < 32) ldst((kc + 1) & 1, (kc + 1) << 5);
        const uint32_t ab = sbase + (uint32_t)(kc & 1) * 32768u;
        const uint32_t bb = ab + 16384u;
        #pragma unroll
        for (int k8 = 0; k8 < 4; k8++) {
            uint32_t aF[4][4], bF[2][4];
            #pragma unroll
            for (int mt = 0; mt < 4; mt++) {
                const int rr = rA + mt * 16;
                ldsm4(aF[mt], ab + ((uint32_t)rr << 7) +
                      ((uint32_t)(((k8 << 1) + chA) ^ (rr & 7)) << 4));
            }
            #pragma unroll
            for (int nt2 = 0; nt2 < 2; nt2++) {
                const int rr = rB + nt2 * 16;
                ldsm4(bF[nt2], bb + ((uint32_t)rr << 7) +
                      ((uint32_t)(((k8 << 1) + chB) ^ (rr & 7)) << 4));
            }
            #pragma unroll
            for (int mt = 0; mt < 4; mt++)
                #pragma unroll
                for (int nt = 0; nt < 4; nt++)
                    mma_tf32(acc[mt][nt], aF[mt], &bF[nt >> 1][(nt & 1) << 1]);
        }
        __syncthreads();
    }

    float* Ct = C + (long long)e * ((long long)Nc * Ic);
    const int g = lane >> 2, t4 = lane & 3;
    #pragma unroll
    for (int mt = 0; mt < 4; mt++) {
        const int row0 = (tm << 7) + warpM * 64 + mt * 16 + g;
        #pragma unroll
        for (int nt = 0; nt < 4; nt++) {
            const int col = (tn << 7) + warpN * 32 + nt * 8 + (t4 << 1);
            float2 v0 = make_float2(gelu_f(acc[mt][nt][0]), gelu_f(acc[mt][nt][1]));
            float2 v1 = make_float2(gelu_f(acc[mt][nt][2]), gelu_f(acc[mt][nt][3]));
            *(float2*)&Ct[(long long)row0 * Ic + col] = v0;
            *(float2*)&Ct[(long long)(row0 + 8) * Ic + col] = v1;
        }
    }
}

__global__ void __launch_bounds__(256) moe_s2_k(
    const float* __restrict__ A, const float* __restrict__ B, float* __restrict__ C,
    const int* __restrict__ idxp, const int* __restrict__ cntp, int e0)
{
    extern __shared__ float dsm[];
    const int e = e0 + blockIdx.z, tm = blockIdx.y, tn = blockIdx.x;
    const int ce = cntp[e];
    if ((tm << 7) >= ce) return;
    const int tid = threadIdx.x, wid = tid >> 5, lane = tid & 31;
    const int warpM = wid >> 2, warpN = wid & 3;
    const uint32_t sbase = smem_u32(dsm);

    const float* At = A + (long long)e * ((long long)Nc * Ic) + ((long long)tm << 7) * Ic;
    const float* Bt = B + (long long)e * ((long long)Cc * Ic) + ((long long)tn << 7) * Ic;

    float acc[4][4][4];
    #pragma unroll
    for (int i = 0; i < 4; i++)
        #pragma unroll
        for (int j = 0; j < 4; j++)
            #pragma unroll
            for (int r = 0; r < 4; r++) acc[i][j][r] = 0.f;

    auto ldst = [&](int s, int k0) {
        const uint32_t ab = sbase + (uint32_t)s * 32768u;
        const uint32_t bb = ab + 16384u;
        #pragma unroll
        for (int k = 0; k < 4; k++) {
            const int u = tid + (k << 8), r = u >> 3, c = u & 7;
            float4 v = *(const float4*)(At + (long long)r * Ic + k0 + (c << 2));
            v = make_float4(tf32r(v.x), tf32r(v.y), tf32r(v.z), tf32r(v.w));
            sts128(ab + ((uint32_t)r << 7) + ((uint32_t)(c ^ (r & 7)) << 4), v);
        }
        #pragma unroll
        for (int k = 0; k < 4; k++) {
            const int u = tid + (k << 8), r = u >> 3, c = u & 7;
            float4 v = *(const float4*)(Bt + (long long)r * Ic + k0 + (c << 2));
            v = make_float4(tf32r(v.x), tf32r(v.y), tf32r(v.z), tf32r(v.w));
            sts128(bb + ((uint32_t)r << 7) + ((uint32_t)(c ^ (r & 7)) << 4), v);
        }
    };

    const int rA = warpM * 64 + ((lane & 8) ? 8 : 0) + (lane & 7);
    const int chA = lane >> 4;
    const int rB = warpN * 32 + ((lane >> 4) << 3) + (lane & 7);
    const int chB = (lane >> 3) & 1;

    ldst(0, 0);
    __syncthreads();
    for (int kc = 0; kc < 8; kc++) {
        if (kc + 1 < 8) ldst((kc + 1) & 1, (kc + 1) << 5);
        const uint32_t ab = sbase + (uint32_t)(kc & 1) * 32768u;
        const uint32_t bb = ab + 16384u;
        #pragma unroll
        for (int k8 = 0; k8 < 4; k8++) {
            uint32_t aF[4][4], bF[2][4];
            #pragma unroll
            for (int mt = 0; mt < 4; mt++) {
                const int rr = rA + mt * 16;
                ldsm4(aF[mt], ab + ((uint32_t)rr << 7) +
                      ((uint32_t)(((k8 << 1) + chA) ^ (rr & 7)) << 4));
            }
            #pragma unroll
            for (int nt2 = 0; nt2 < 2; nt2++) {
                const int rr = rB + nt2 * 16;
                ldsm4(bF[nt2], bb + ((uint32_t)rr << 7) +
                      ((uint32_t)(((k8 << 1) + chB) ^ (rr & 7)) << 4));
            }
            #pragma unroll
            for (int mt = 0; mt < 4; mt++)
                #pragma unroll
                for (int nt = 0; nt < 4; nt++)
                    mma_tf32(acc[mt][nt], aF[mt], &bF[nt >> 1][(nt & 1) << 1]);
        }
        __syncthreads();
    }

    const int g = lane >> 2, t4 = lane & 3;
    #pragma unroll
    for (int mt = 0; mt < 4; mt++) {
        const int rg0 = (tm << 7) + warpM * 64 + mt * 16 + g;
        const int rg1 = rg0 + 8;
        const bool a0 = rg0 < ce, a1 = rg1 < ce;
        const int n0 = a0 ? idxp[e * Nc + rg0] : 0;
        const int n1 = a1 ? idxp[e * Nc + rg1] : 0;
        #pragma unroll
        for (int nt = 0; nt < 4; nt++) {
            const int col = (tn << 7) + warpN * 32 + nt * 8 + (t4 << 1);
            if (a0)
                *(float2*)&C[((long long)n0 * Ec + e) * Cc + col] =
                    make_float2(acc[mt][nt][0], acc[mt][nt][1]);
            if (a1)
                *(float2*)&C[((long long)n1 * Ec + e) * Cc + col] =
                    make_float2(acc[mt][nt][2], acc[mt][nt][3]);
        }
    }
}

__global__ void zero_cnt_k(int* cnt) { if (threadIdx.x < Ec) cnt[threadIdx.x] = 0; }

__global__ void __launch_bounds__(256) zero_eo_k(float4* __restrict__ p, long long n4)
{
    long long i = (long long)blockIdx.x * 256 + threadIdx.x;
    const long long stride = (long long)gridDim.x * 256;
    for (; i < n4; i += stride) p[i] = make_float4(0.f, 0.f, 0.f, 0.f);
}

__global__ void __launch_bounds__(256) transpose_k(
    const float* __restrict__ in, float* __restrict__ out, int R, int C)
{
    __shared__ float t[32][33];
    const long long zo = (long long)blockIdx.z * R * C;
    const int c0 = blockIdx.x << 5, r0 = blockIdx.y << 5;
    const int tx = threadIdx.x & 31, ty = threadIdx.x >> 5;
    #pragma unroll
    for (int k = 0; k < 32; k += 8)
        t[ty + k][tx] = in[zo + (long long)(r0 + ty + k) * C + c0 + tx];
    __syncthreads();
    #pragma unroll
    for (int k = 0; k < 32; k += 8)
        out[zo + (long long)(c0 + ty + k) * R + r0 + tx] = t[tx][ty + k];
}

// ------- fp32 SGEMM, f32x2, BK=16 double-buffered (exact, order-preserving) -------
__device__ __forceinline__ void sgemm_core2(
    const float* __restrict__ A, const float* __restrict__ B,
    int K, int Np, int brow, int bcol, ull acc2[8][4])
{
    __shared__ float As[2][16][128];
    __shared__ float Bs[2][16][128];
    const int tid = threadIdx.x;
    const int ar = tid & 127, ac = (tid >> 7) << 3;
    const int bk = tid >> 4, bcl = (tid & 15) << 3;
    const int tx = tid & 15, ty = tid >> 4;
    const float* Arow = A + (long long)(brow + ar) * K + ac;
    const float* Bbase = B + bcol + bcl + (long long)bk * Np;

    #pragma unroll
    for (int i = 0; i < 8; i++)
        #pragma unroll
        for (int p = 0; p < 4; p++) acc2[i][p] = 0ull;

    float4 la0, la1, lb0, lb1;
    auto ldg = [&](int k0) {
        la0 = *(const float4*)(Arow + k0);
        la1 = *(const float4*)(Arow + k0 + 4);
        lb0 = *(const float4*)(Bbase + (long long)k0 * Np);
        lb1 = *(const float4*)(Bbase + (long long)k0 * Np + 4);
    };
    auto sts = [&](int s) {
        As[s][ac+0][ar] = la0.x; As[s][ac+1][ar] = la0.y;
        As[s][ac+2][ar] = la0.z; As[s][ac+3][ar] = la0.w;
        As[s][ac+4][ar] = la1.x; As[s][ac+5][ar] = la1.y;
        As[s][ac+6][ar] = la1.z; As[s][ac+7][ar] = la1.w;
        *(float4*)&Bs[s][bk][bcl] = lb0;
        *(float4*)&Bs[s][bk][bcl + 4] = lb1;
    };

    const int NC16 = K >> 4;
    ldg(0); sts(0);
    __syncthreads();
    for (int kc = 0; kc < NC16; kc++) {
        if (kc + 1 < NC16) ldg((kc + 1) << 4);
        const int s = kc & 1;
        #pragma unroll
        for (int kk = 0; kk < 16; kk++) {
            float4 a0 = *(const float4*)&As[s][kk][ty << 3];
            float4 a1 = *(const float4*)&As[s][kk][(ty << 3) + 4];
            ulonglong2 b01 = *(const ulonglong2*)&Bs[s][kk][tx << 3];
            ulonglong2 b23 = *(const ulonglong2*)&Bs[s][kk][(tx << 3) + 4];
            ull a2[8];
            a2[0]=dup2(a0.x); a2[1]=dup2(a0.y); a2[2]=dup2(a0.z); a2[3]=dup2(a0.w);
            a2[4]=dup2(a1.x); a2[5]=dup2(a1.y); a2[6]=dup2(a1.z); a2[7]=dup2(a1.w);
            #pragma unroll
            for (int i = 0; i < 8; i++) {
                fma2(acc2[i][0], a2[i], b01.x);
                fma2(acc2[i][1], a2[i], b01.y);
                fma2(acc2[i][2], a2[i], b23.x);
                fma2(acc2[i][3], a2[i], b23.y);
            }
        }
        if (kc + 1 < NC16) sts((kc + 1) & 1);
        __syncthreads();
    }
}

__global__ void __launch_bounds__(256, 2) gemm_res_k(
    const float* __restrict__ A, const float* __restrict__ B, float* __restrict__ C,
    const float* __restrict__ res)
{
    const int brow = blockIdx.y << 7, bcol = blockIdx.x << 7;
    ull acc2[8][4];
    sgemm_core2(A, B, Cc, Cc, brow, bcol, acc2);
    const int tx = threadIdx.x & 15, ty = threadIdx.x >> 4;
    #pragma unroll
    for (int i = 0; i < 8; i++) {
        const int row = brow + (ty << 3) + i;
        #pragma unroll
        for (int p = 0; p < 4; p += 2) {
            const int col = bcol + (tx << 3) + (p << 1);
            float2 e0 = unpk(acc2[i][p]), e1 = unpk(acc2[i][p + 1]);
            float4 v = make_float4(e0.x, e0.y, e1.x, e1.y);
            float4 rv = *(const float4*)&res[(long long)row * Cc + col];
            v.x += rv.x; v.y += rv.y; v.z += rv.z; v.w += rv.w;
            *(float4*)&C[(long long)row * Cc + col] = v;
        }
    }
}

__global__ void __launch_bounds__(256, 2) gemm_qkv_k(
    const float* __restrict__ A,
    const float* __restrict__ b0, const float* __restrict__ b1, const float* __restrict__ b2,
    float* __restrict__ c0, float* __restrict__ c1, float* __restrict__ c2)
{
    const int z = blockIdx.z;
    const float* B = (z == 0) ? b0 : (z == 1) ? b1 : b2;
    float* C = (z == 0) ? c0 : (z == 1) ? c1 : c2;
    const int brow = blockIdx.y << 7, bcol = blockIdx.x << 7;
    ull acc2[8][4];
    sgemm_core2(A, B, Cc, Cc, brow, bcol, acc2);
    const int tx = threadIdx.x & 15, ty = threadIdx.x >> 4;
    #pragma unroll
    for (int i = 0; i < 8; i++) {
        const int row = brow + (ty << 3) + i;
        #pragma unroll
        for (int p = 0; p < 4; p += 2) {
            const int col = bcol + (tx << 3) + (p << 1);
            float2 e0 = unpk(acc2[i][p]), e1 = unpk(acc2[i][p + 1]);
            *(float4*)&C[(long long)row * Cc + col] = make_float4(e0.x, e0.y, e1.x, e1.y);
        }
    }
}

// ------- flash attention: paired q-tiles, double-buffered K/V (2 syncs/iter) -------
#define AP 68
#define SM_ATTN2 (6 * 64 * AP * 4)   // Q + 2K + 2V + P = 104448 B
__global__ void __launch_bounds__(256) attn2_k(
    const float* __restrict__ Q, const float* __restrict__ K,
    const float* __restrict__ V, float* __restrict__ O)
{
    extern __shared__ float sm[];
    float* Qs = sm;
    float* Kb[2] = { sm + 64 * AP, sm + 2 * 64 * AP };
    float* Vb[2] = { sm + 3 * 64 * AP, sm + 4 * 64 * AP };
    float* Ps = sm + 5 * 64 * AP;
    const int h = blockIdx.y, b = blockIdx.z;
    const int tid = threadIdx.x;
    const int tx = tid & 15, ty = tid >> 4;
    const long long base = ((long long)b * Tc) * Cc + h * Dc;
    const int lr = tid >> 4;
    const int lc = (tid & 15) << 2;

    #pragma unroll
    for (int seg = 0; seg < 2; seg++) {
        const int qt = seg ? 15 - (int)blockIdx.x : (int)blockIdx.x;
        __syncthreads();
        #pragma unroll
        for (int rep = 0; rep < 4; rep++) {
            const int r = lr + (rep << 4);
            float4 v = *(const float4*)&Q[base + (long long)(qt * 64 + r) * Cc + lc];
            v.x *= 0.125f; v.y *= 0.125f; v.z *= 0.125f; v.w *= 0.125f;
            *(float4*)&Qs[r * AP + lc] = v;
        }

        ull acc2[4][2];
        float mi[4], li[4];
        #pragma unroll
        for (int i = 0; i < 4; i++) { acc2[i][0] = 0ull; acc2[i][1] = 0ull; mi[i] = -1e30f; li[i] = 0.f; }

        float4 kr[4], vr[4];
        #pragma unroll
        for (int rep = 0; rep < 4; rep++) {
            const int r = lr + (rep << 4);
            kr[rep] = *(const float4*)&K[base + (long long)r * Cc + lc];
            vr[rep] = *(const float4*)&V[base + (long long)r * Cc + lc];
        }

        for (int kt = 0; kt <= qt; kt++) {
            const int buf = kt & 1;
            float* Ks = Kb[buf];
            float* Vs = Vb[buf];
            #pragma unroll
            for (int rep = 0; rep < 4; rep++) {
                const int r = lr + (rep << 4);
                *(float4*)&Ks[r * AP + lc] = kr[rep];
                *(float4*)&Vs[r * AP + lc] = vr[rep];
            }
            __syncthreads();   // K/V ready; prev P-reads done
            if (kt < qt) {
                #pragma unroll
                for (int rep = 0; rep < 4; rep++) {
                    const int r = lr + (rep << 4);
                    kr[rep] = *(const float4*)&K[base + (long long)((kt + 1) * 64 + r) * Cc + lc];
                    vr[rep] = *(const float4*)&V[base + (long long)((kt + 1) * 64 + r) * Cc + lc];
                }
            }
            ull s2[4][4];
            #pragma unroll
            for (int i = 0; i < 4; i++)
                #pragma unroll
                for (int j = 0; j < 4; j++) s2[i][j] = 0ull;
            #pragma unroll 4
            for (int d4 = 0; d4 < 16; d4++) {
                ulonglong2 la[4], lb[4];
                #pragma unroll
                for (int i = 0; i < 4; i++)
                    la[i] = *(const ulonglong2*)&Qs[((ty << 2) + i) * AP + (d4 << 2)];
                #pragma unroll
                for (int j = 0; j < 4; j++)
                    lb[j] = *(const ulonglong2*)&Ks[(tx + (j << 4)) * AP + (d4 << 2)];
                #pragma unroll
                for (int i = 0; i < 4; i++)
                    #pragma unroll
                    for (int j = 0; j < 4; j++) {
                        fma2(s2[i][j], la[i].x, lb[j].x);
                        fma2(s2[i][j], la[i].y, lb[j].y);
                    }
            }
            const bool diag = (kt == qt);
            #pragma unroll
            for (int i = 0; i < 4; i++) {
                float p[4];
                float mloc = -1e30f;
                #pragma unroll
                for (int j = 0; j < 4; j++) {
                    float2 u = unpk(s2[i][j]);
                    float sv = u.x + u.y;
                    if (diag && (tx + (j << 4)) > ((ty << 2) + i)) sv = -1e30f;
                    p[j] = sv;
                    mloc = fmaxf(mloc, sv);
                }
                mloc = fmaxf(mloc, __shfl_xor_sync(0xffffffffu, mloc, 1));
                mloc = fmaxf(mloc, __shfl_xor_sync(0xffffffffu, mloc, 2));
                mloc = fmaxf(mloc, __shfl_xor_sync(0xffffffffu, mloc, 4));
                mloc = fmaxf(mloc, __shfl_xor_sync(0xffffffffu, mloc, 8));
                const float mnew = fmaxf(mi[i], mloc);
                const float alpha = __expf(mi[i] - mnew);
                mi[i] = mnew;
                float ps = 0.f;
                #pragma unroll
                for (int j = 0; j < 4; j++) { p[j] = __expf(p[j] - mnew); ps += p[j]; }
                ps += __shfl_xor_sync(0xffffffffu, ps, 1);
                ps += __shfl_xor_sync(0xffffffffu, ps, 2);
                ps += __shfl_xor_sync(0xffffffffu, ps, 4);
                ps += __shfl_xor_sync(0xffffffffu, ps, 8);
                li[i] = li[i] * alpha + ps;
                const ull ad = dup2(alpha);
                acc2[i][0] = mul2(acc2[i][0], ad);
                acc2[i][1] = mul2(acc2[i][1], ad);
                float* pr = &Ps[((ty << 2) + i) * AP + tx];
                pr[0] = p[0]; pr[16] = p[1]; pr[32] = p[2]; pr[48] = p[3];
            }
            __syncthreads();   // P ready
            #pragma unroll 4
            for (int j4 = 0; j4 < 16; j4++) {
                float4 pa[4];
                #pragma unroll
                for (int i = 0; i < 4; i++)
                    pa[i] = *(const float4*)&Ps[((ty << 2) + i) * AP + (j4 << 2)];
                #pragma unroll
                for (int jj = 0; jj < 4; jj++) {
                    const ulonglong2 vb = *(const ulonglong2*)&Vs[((j4 << 2) + jj) * AP + (tx << 2)];
                    #pragma unroll
                    for (int i = 0; i < 4; i++) {
                        const float* pf = (const float*)&pa[i];
                        const ull pd = dup2(pf[jj]);
                        fma2(acc2[i][0], pd, vb.x);
                        fma2(acc2[i][1], pd, vb.y);
                    }
                }
            }
        }
        #pragma unroll
        for (int i = 0; i < 4; i++) {
            const float inv = 1.f / li[i];
            float2 e0 = unpk(acc2[i][0]), e1 = unpk(acc2[i][1]);
            float4 v = make_float4(e0.x * inv, e0.y * inv, e1.x * inv, e1.y * inv);
            *(float4*)&O[base + (long long)(qt * 64 + (ty << 2) + i) * Cc + (tx << 2)] = v;
        }
    }
}

__global__ void __launch_bounds__(256) ln_k(
    const float* __restrict__ x, const float* __restrict__ g,
    const float* __restrict__ b, float* __restrict__ o)
{
    const int n = blockIdx.x, tid = threadIdx.x;
    const long long rb = (long long)n << 10;
    const int c = tid << 2;
    float4 v = *(const float4*)&x[rb + c];
    float s = v.x + v.y + v.z + v.w;
    float ss = v.x*v.x + v.y*v.y + v.z*v.z + v.w*v.w;
    #pragma unroll
    for (int off = 16; off; off >>= 1) {
        s  += __shfl_xor_sync(0xffffffffu, s, off);
        ss += __shfl_xor_sync(0xffffffffu, ss, off);
    }
    __shared__ float rs[8], rss[8], mv[2];
    const int w = tid >> 5, lane = tid & 31;
    if (!lane) { rs[w] = s; rss[w] = ss; }
    __syncthreads();
    if (tid == 0) {
        float S = 0, SS = 0;
        #pragma unroll
        for (int i = 0; i < 8; i++) { S += rs[i]; SS += rss[i]; }
        const float mean = S * (1.f/1024.f);
        const float var = SS * (1.f/1024.f) - mean * mean;
        mv[0] = mean; mv[1] = rsqrtf(var + 1e-5f);
    }
    __syncthreads();
    const float mean = mv[0], rstd = mv[1];
    float4 gg = *(const float4*)&g[c], bb = *(const float4*)&b[c];
    float4 ov;
    ov.x = (v.x-mean)*rstd*gg.x + bb.x; ov.y = (v.y-mean)*rstd*gg.y + bb.y;
    ov.z = (v.z-mean)*rstd*gg.z + bb.z; ov.w = (v.w-mean)*rstd*gg.w + bb.w;
    *(float4*)&o[rb + c] = ov;
}

__global__ void __launch_bounds__(256) colnorm_k(
    const float* __restrict__ sim, float* __restrict__ colinv)
{
    const int e = blockIdx.x, tid = threadIdx.x;
    float s = 0.f;
    for (int cc = tid; cc < 1024; cc += 256) {
        const float v = sim[cc * 16 + e];
        s = fmaf(v, v, s);
    }
    #pragma unroll
    for (int off = 16; off; off >>= 1) s += __shfl_xor_sync(0xffffffffu, s, off);
    __shared__ float rs[8];
    const int w = tid >> 5, lane = tid & 31;
    if (!lane) rs[w] = s;
    __syncthreads();
    if (tid == 0) {
        float S = 0;
        #pragma unroll
        for (int i = 0; i < 8; i++) S += rs[i];
        colinv[e] = rsqrtf(S);
    }
}

// ------- fused LN2 + routing scores + mask + kpt + expert compaction -------
__global__ void __launch_bounds__(256) lnscore_k(
    const float* __restrict__ x1, const float* __restrict__ g, const float* __restrict__ b,
    const float* __restrict__ sim, const float* __restrict__ thr,
    const float* __restrict__ colinv, float* __restrict__ oh2,
    float* __restrict__ oscores, float* __restrict__ okpt, float* __restrict__ maskb,
    int* __restrict__ cnt, int* __restrict__ idxp)
{
    const int n = blockIdx.x, tid = threadIdx.x;
    const long long rb = (long long)n << 10;
    const int c = tid << 2;
    const int w = tid >> 5, lane = tid & 31;

    float4 xv = *(const float4*)&x1[rb + c];
    {
        float s  = xv.x + xv.y + xv.z + xv.w;
        float ss = xv.x*xv.x + xv.y*xv.y + xv.z*xv.z + xv.w*xv.w;
        #pragma unroll
        for (int off = 16; off; off >>= 1) {
            s  += __shfl_xor_sync(0xffffffffu, s, off);
            ss += __shfl_xor_sync(0xffffffffu, ss, off);
        }
        __shared__ float rs0[8], rss0[8], mv[2];
        if (!lane) { rs0[w] = s; rss0[w] = ss; }
        __syncthreads();
        if (tid == 0) {
            float S = 0, SS = 0;
            #pragma unroll
            for (int i = 0; i < 8; i++) { S += rs0[i]; SS += rss0[i]; }
            const float mean = S * (1.f/1024.f);
            const float var = SS * (1.f/1024.f) - mean * mean;
            mv[0] = mean; mv[1] = rsqrtf(var + 1e-5f);
        }
        __syncthreads();
        const float mean = mv[0], rstd = mv[1];
        float4 gg = *(const float4*)&g[c], bb = *(const float4*)&b[c];
        xv.x = (xv.x-mean)*rstd*gg.x + bb.x; xv.y = (xv.y-mean)*rstd*gg.y + bb.y;
        xv.z = (xv.z-mean)*rstd*gg.z + bb.z; xv.w = (xv.w-mean)*rstd*gg.w + bb.w;
        *(float4*)&oh2[rb + c] = xv;
    }
    __syncthreads();

    float ss = xv.x*xv.x + xv.y*xv.y + xv.z*xv.z + xv.w*xv.w;
    float accd[16];
    #pragma unroll
    for (int e = 0; e < 16; e++) accd[e] = 0.f;
    const float hv[4] = {xv.x, xv.y, xv.z, xv.w};
    #pragma unroll
    for (int cc = 0; cc < 4; cc++) {
        const float* sr = &sim[(long long)(c + cc) << 4];
        #pragma unroll
        for (int e = 0; e < 16; e++) accd[e] = fmaf(hv[cc], sr[e], accd[e]);
    }
    #pragma unroll
    for (int off = 16; off; off >>= 1) ss += __shfl_xor_sync(0xffffffffu, ss, off);
    __shared__ float rs[8];
    __shared__ float red[16 * 8];
    __shared__ float smask[16];
    __shared__ float srn;
    if (!lane) rs[w] = ss;
    #pragma unroll
    for (int e = 0; e < 16; e++) {
        float t = accd[e];
        #pragma unroll
        for (int off = 16; off; off >>= 1) t += __shfl_xor_sync(0xffffffffu, t, off);
        if (!lane) red[e * 8 + w] = t;
    }
    __syncthreads();
    if (tid == 0) {
        float S = 0;
        #pragma unroll
        for (int i = 0; i < 8; i++) S += rs[i];
        srn = rsqrtf(S);
    }
    __syncthreads();
    if (tid < 16) {
        float sum = 0;
        #pragma unroll
        for (int i = 0; i < 8; i++) sum += red[tid * 8 + i];
        const float sc = sum * srn * colinv[tid];
        oscores[(n << 4) + tid] = sc;
        const float m = (sc > thr[0]) ? 1.f : 0.f;
        maskb[(n << 4) + tid] = m;
        smask[tid] = m;
        if (m != 0.f) {
            const int pos = atomicAdd(&cnt[tid], 1);
            idxp[tid * Nc + pos] = n;
        }
    }
    __syncthreads();
    if (tid == 0) {
        float kc = 0;
        #pragma unroll
        for (int e = 0; e < 16; e++) kc += smask[e];
        okpt[n] = kc;
    }
}

__global__ void __launch_bounds__(256) final_k(
    const float* __restrict__ x1, const float* __restrict__ eo,
    const float* __restrict__ maskb, float* __restrict__ ox)
{
    const int n = blockIdx.x, tid = threadIdx.x;
    __shared__ float mk[16];
    if (tid < 16) mk[tid] = maskb[(n << 4) + tid];
    __syncthreads();
    const int c = tid << 2;
    const long long rb = (long long)n << 10;
    float4 v = *(const float4*)&x1[rb + c];
    #pragma unroll
    for (int e = 0; e < 16; e++) {
        if (mk[e] != 0.f) {
            const float4 wv = *(const float4*)&eo[(((long long)(n * 16 + e)) << 10) + c];
            v.x += wv.x; v.y += wv.y; v.z += wv.z; v.w += wv.w;
        }
    }
    *(float4*)&ox[rb + c] = v;
}

extern "C" void kernel_launch(void* const* d_in, const int* in_sizes, int n_in,
                              void* d_out, int out_size)
{
    (void)in_sizes; (void)n_in;
    const float* x    = (const float*)d_in[0];
    const float* ln1g = (const float*)d_in[1];
    const float* ln1b = (const float*)d_in[2];
    const float* ln2g = (const float*)d_in[3];
    const float* ln2b = (const float*)d_in[4];
    const float* wq   = (const float*)d_in[5];
    const float* wk   = (const float*)d_in[6];
    const float* wv   = (const float*)d_in[7];
    const float* wo   = (const float*)d_in[8];
    const float* sim  = (const float*)d_in[9];
    const float* thr  = (const float*)d_in[10];
    const float* w1   = (const float*)d_in[11];
    const float* w2   = (const float*)d_in[12];

    float *ph, *pq, *pk, *pv, *pao, *px1, *pmid, *pw1t, *pw2t, *peos, *pmask, *pcol, *pssc, *pkpt;
    int *pcnt, *pidx;
    cudaGetSymbolAddress((void**)&ph, g_h);
    cudaGetSymbolAddress((void**)&pq, g_q);
    cudaGetSymbolAddress((void**)&pk, g_k);
    cudaGetSymbolAddress((void**)&pv, g_v);
    cudaGetSymbolAddress((void**)&pao, g_ao);
    cudaGetSymbolAddress((void**)&px1, g_x1);
    cudaGetSymbolAddress((void**)&pmid, g_mid);
    cudaGetSymbolAddress((void**)&pw1t, g_w1t);
    cudaGetSymbolAddress((void**)&pw2t, g_w2t);
    cudaGetSymbolAddress((void**)&peos, g_eo_scr);
    cudaGetSymbolAddress((void**)&pmask, g_mask);
    cudaGetSymbolAddress((void**)&pcol, g_colinv);
    cudaGetSymbolAddress((void**)&pssc, g_scores_scr);
    cudaGetSymbolAddress((void**)&pkpt, g_kpt_scr);
    cudaGetSymbolAddress((void**)&pcnt, g_cnt);
    cudaGetSymbolAddress((void**)&pidx, g_idx);

    const long long XN  = (long long)Nc * Cc;
    const long long SCN = (long long)Nc * Ec;
    const long long EON = (long long)Nc * Ec * Cc;
    const bool full = ((long long)out_size >= XN + SCN + EON + Nc);
    float* out   = (float*)d_out;
    float* o_x   = out;
    float* o_sc  = full ? out + XN : pssc;
    float* o_eo  = full ? out + XN + SCN : peos;
    float* o_kpt = full ? out + XN + SCN + EON : pkpt;

    cudaFuncSetAttribute(attn2_k, cudaFuncAttributeMaxDynamicSharedMemorySize, SM_ATTN2);
    cudaFuncSetAttribute(moe_g1_k, cudaFuncAttributeMaxDynamicSharedMemorySize, MOE_SMEM);
    cudaFuncSetAttribute(moe_s2_k, cudaFuncAttributeMaxDynamicSharedMemorySize, MOE_SMEM);

    // ---- one side stream (same footprint as the passing R7/R8 pattern) ----
    cudaStream_t s2;
    cudaStreamCreateWithFlags(&s2, cudaStreamNonBlocking);
    cudaEvent_t ev1, evPrep, evScore, evMoe;
    cudaEventCreateWithFlags(&ev1, cudaEventDisableTiming);
    cudaEventCreateWithFlags(&evPrep, cudaEventDisableTiming);
    cudaEventCreateWithFlags(&evScore, cudaEventDisableTiming);
    cudaEventCreateWithFlags(&evMoe, cudaEventDisableTiming);

    cudaEventRecord(ev1, 0);
    cudaStreamWaitEvent(s2, ev1, 0);
    zero_eo_k<<<2048, 256, 0, s2>>>((float4*)o_eo, EON / 4);
    zero_cnt_k<<<1, 32, 0, s2>>>(pcnt);
    transpose_k<<<dim3(8, 32, 16), 256, 0, s2>>>(w1, pw1t, Cc, Ic);
    transpose_k<<<dim3(32, 8, 16), 256, 0, s2>>>(w2, pw2t, Ic, Cc);
    colnorm_k<<<16, 256, 0, s2>>>(sim, pcol);
    cudaEventRecord(evPrep, s2);

    // ---- main chain ----
    ln_k<<<Nc, 256>>>(x, ln1g, ln1b, ph);
    gemm_qkv_k<<<dim3(8, 16, 3), 256>>>(ph, wq, wk, wv, pq, pk, pv);
    attn2_k<<<dim3(8, Hc, Bc), 256, SM_ATTN2>>>(pq, pk, pv, pao);
    gemm_res_k<<<dim3(8, 16, 1), 256>>>(pao, wo, px1, x);

    cudaStreamWaitEvent(0, evPrep, 0);
    lnscore_k<<<Nc, 256>>>(px1, ln2g, ln2b, sim, thr, pcol, ph,
                           o_sc, o_kpt, pmask, pcnt, pidx);
    cudaEventRecord(evScore, 0);

    // ---- 2-way split MoE: experts 0-7 on default stream, 8-15 on s2 ----
    cudaStreamWaitEvent(s2, evScore, 0);
    moe_g1_k<<<dim3(2, 16, 8), 256, MOE_SMEM, s2>>>(ph, pw1t, pmid, pidx, pcnt, 8);
    moe_s2_k<<<dim3(8, 16, 8), 256, MOE_SMEM, s2>>>(pmid, pw2t, o_eo, pidx, pcnt, 8);
    cudaEventRecord(evMoe, s2);

    moe_g1_k<<<dim3(2, 16, 8), 256, MOE_SMEM>>>(ph, pw1t, pmid, pidx, pcnt, 0);
    moe_s2_k<<<dim3(8, 16, 8), 256, MOE_SMEM>>>(pmid, pw2t, o_eo, pidx, pcnt, 0);

    cudaStreamWaitEvent(0, evMoe, 0);
    final_k<<<Nc, 256>>>(px1, o_eo, pmask, o_x);
}

// round 11
// speedup vs baseline: 1.0267x; 1.0267x over previous
#include <cuda_runtime.h>
#include <math.h>
#include <stdint.h>

#define Bc 2
#define Tc 1024
#define Cc 1024
#define Hc 16
#define Dc 64
#define Ec 16
#define Ic 256
#define Nc (Bc*Tc)

typedef unsigned long long ull;

__device__ float g_h  [Nc*Cc];
__device__ float g_q  [Nc*Cc];
__device__ float g_k  [Nc*Cc];
__device__ float g_v  [Nc*Cc];
__device__ float g_ao [Nc*Cc];
__device__ float g_x1 [Nc*Cc];
__device__ float g_mid[(long long)Ec*Nc*Ic];
__device__ float g_w1t[(long long)Ec*Ic*Cc];
__device__ float g_w2t[(long long)Ec*Cc*Ic];
__device__ float g_eo_scr[(long long)Nc*Ec*Cc];
__device__ float g_mask[Nc*Ec];
__device__ float g_colinv[Ec];
__device__ float g_scores_scr[Nc*Ec];
__device__ float g_kpt_scr[Nc];
__device__ int   g_cnt[Ec];
__device__ int   g_idx[Ec*Nc];

__device__ __forceinline__ float gelu_f(float x) {
    return 0.5f * x * (1.0f + erff(x * 0.70710678118654752440f));
}
__device__ __forceinline__ uint32_t smem_u32(const void* p) {
    uint32_t a;
    asm("{ .reg .u64 t; cvta.to.shared.u64 t, %1; cvt.u32.u64 %0, t; }" : "=r"(a) : "l"(p));
    return a;
}
__device__ __forceinline__ float tf32r(float x) {
    float o; asm("cvt.rna.tf32.f32 %0, %1;" : "=f"(o) : "f"(x)); return o;
}
__device__ __forceinline__ void sts128(uint32_t a, float4 v) {
    asm volatile("st.shared.v4.b32 [%0], {%1,%2,%3,%4};" ::
                 "r"(a), "f"(v.x), "f"(v.y), "f"(v.z), "f"(v.w) : "memory");
}
__device__ __forceinline__ void ldsm4(uint32_t (&d)[4], uint32_t addr) {
    asm volatile("ldmatrix.sync.aligned.m8n8.x4.shared.b16 {%0,%1,%2,%3}, [%4];"
                 : "=r"(d[0]), "=r"(d[1]), "=r"(d[2]), "=r"(d[3]) : "r"(addr));
}
__device__ __forceinline__ void mma_tf32(float (&c)[4], const uint32_t (&a)[4], const uint32_t* b) {
    asm volatile("mma.sync.aligned.m16n8k8.row.col.f32.tf32.tf32.f32 "
                 "{%0,%1,%2,%3}, {%4,%5,%6,%7}, {%8,%9}, {%0,%1,%2,%3};"
                 : "+f"(c[0]), "+f"(c[1]), "+f"(c[2]), "+f"(c[3])
                 : "r"(a[0]), "r"(a[1]), "r"(a[2]), "r"(a[3]), "r"(b[0]), "r"(b[1]));
}
__device__ __forceinline__ ull dup2(float x) {
    ull r; asm("mov.b64 %0, {%1,%1};" : "=l"(r) : "f"(x)); return r;
}
__device__ __forceinline__ void fma2(ull &c, ull a, ull b) {
    asm("fma.rn.f32x2 %0, %1, %2, %0;" : "+l"(c) : "l"(a), "l"(b));
}
__device__ __forceinline__ ull mul2(ull a, ull b) {
    ull d; asm("mul.rn.f32x2 %0, %1, %2;" : "=l"(d) : "l"(a), "l"(b)); return d;
}
__device__ __forceinline__ float2 unpk(ull v) {
    float2 f; asm("mov.b64 {%0,%1}, %2;" : "=f"(f.x), "=f"(f.y) : "l"(v)); return f;
}

// ================= MoE tf32 MMA (gathered / scattered, expert-offset batched) =================
#define MOE_SMEM 65536

__global__ void __launch_bounds__(256) moe_g1_k(
    const float* __restrict__ A, const float* __restrict__ B, float* __restrict__ C,
    const int* __restrict__ idxp, const int* __restrict__ cntp, int e0)
{
    extern __shared__ float dsm[];
    const int e = e0 + blockIdx.z, tm = blockIdx.y, tn = blockIdx.x;
    const int ce = cntp[e];
    if ((tm << 7) >= ce) return;
    const int tid = threadIdx.x, wid = tid >> 5, lane = tid & 31;
    const int warpM = wid >> 2, warpN = wid & 3;
    const uint32_t sbase = smem_u32(dsm);

    int srcA[4];
    #pragma unroll
    for (int k = 0; k < 4; k++) {
        const int r = (tid + (k << 8)) >> 3;
        int gr = (tm << 7) + r;
        if (gr >= ce) gr = ce - 1;
        srcA[k] = idxp[e * Nc + gr];
    }
    const float* Bt = B + (long long)e * ((long long)Ic * Cc) + ((long long)tn << 7) * Cc;

    float acc[4][4][4];
    #pragma unroll
    for (int i = 0; i < 4; i++)
        #pragma unroll
        for (int j = 0; j < 4; j++)
            #pragma unroll
            for (int r = 0; r < 4; r++) acc[i][j][r] = 0.f;

    auto ldst = [&](int s, int k0) {
        const uint32_t ab = sbase + (uint32_t)s * 32768u;
        const uint32_t bb = ab + 16384u;
        #pragma unroll
        for (int k = 0; k < 4; k++) {
            const int u = tid + (k << 8), r = u >> 3, c = u & 7;
            float4 v = *(const float4*)(A + (long long)srcA[k] * Cc + k0 + (c << 2));
            v = make_float4(tf32r(v.x), tf32r(v.y), tf32r(v.z), tf32r(v.w));
            sts128(ab + ((uint32_t)r << 7) + ((uint32_t)(c ^ (r & 7)) << 4), v);
        }
        #pragma unroll
        for (int k = 0; k < 4; k++) {
            const int u = tid + (k << 8), r = u >> 3, c = u & 7;
            float4 v = *(const float4*)(Bt + (long long)r * Cc + k0 + (c << 2));
            v = make_float4(tf32r(v.x), tf32r(v.y), tf32r(v.z), tf32r(v.w));
            sts128(bb + ((uint32_t)r << 7) + ((uint32_t)(c ^ (r & 7)) << 4), v);
        }
    };

    const int rA = warpM * 64 + ((lane & 8) ? 8 : 0) + (lane & 7);
    const int chA = lane >> 4;
    const int rB = warpN * 32 + ((lane >> 4) << 3) + (lane & 7);
    const int chB = (lane >> 3) & 1;

    ldst(0, 0);
    __syncthreads();
    for (int kc = 0; kc < 32; kc++) {
        if (kc + 1 < 32) ldst((kc + 1) & 1, (kc + 1) << 5);
        const uint32_t ab = sbase + (uint32_t)(kc & 1) * 32768u;
        const uint32_t bb = ab + 16384u;
        #pragma unroll
        for (int k8 = 0; k8 < 4; k8++) {
            uint32_t aF[4][4], bF[2][4];
            #pragma unroll
            for (int mt = 0; mt < 4; mt++) {
                const int rr = rA + mt * 16;
                ldsm4(aF[mt], ab + ((uint32_t)rr << 7) +
                      ((uint32_t)(((k8 << 1) + chA) ^ (rr & 7)) << 4));
            }
            #pragma unroll
            for (int nt2 = 0; nt2 < 2; nt2++) {
                const int rr = rB + nt2 * 16;
                ldsm4(bF[nt2], bb + ((uint32_t)rr << 7) +
                      ((uint32_t)(((k8 << 1) + chB) ^ (rr & 7)) << 4));
            }
            #pragma unroll
            for (int mt = 0; mt < 4; mt++)
                #pragma unroll
                for (int nt = 0; nt < 4; nt++)
                    mma_tf32(acc[mt][nt], aF[mt], &bF[nt >> 1][(nt & 1) << 1]);
        }
        __syncthreads();
    }

    float* Ct = C + (long long)e * ((long long)Nc * Ic);
    const int g = lane >> 2, t4 = lane & 3;
    #pragma unroll
    for (int mt = 0; mt < 4; mt++) {
        const int row0 = (tm << 7) + warpM * 64 + mt * 16 + g;
        #pragma unroll
        for (int nt = 0; nt < 4; nt++) {
            const int col = (tn << 7) + warpN * 32 + nt * 8 + (t4 << 1);
            float2 v0 = make_float2(gelu_f(acc[mt][nt][0]), gelu_f(acc[mt][nt][1]));
            float2 v1 = make_float2(gelu_f(acc[mt][nt][2]), gelu_f(acc[mt][nt][3]));
            *(float2*)&Ct[(long long)row0 * Ic + col] = v0;
            *(float2*)&Ct[(long long)(row0 + 8) * Ic + col] = v1;
        }
    }
}

__global__ void __launch_bounds__(256) moe_s2_k(
    const float* __restrict__ A, const float* __restrict__ B, float* __restrict__ C,
    const int* __restrict__ idxp, const int* __restrict__ cntp, int e0)
{
    extern __shared__ float dsm[];
    const int e = e0 + blockIdx.z, tm = blockIdx.y, tn = blockIdx.x;
    const int ce = cntp[e];
    if ((tm << 7) >= ce) return;
    const int tid = threadIdx.x, wid = tid >> 5, lane = tid & 31;
    const int warpM = wid >> 2, warpN = wid & 3;
    const uint32_t sbase = smem_u32(dsm);

    const float* At = A + (long long)e * ((long long)Nc * Ic) + ((long long)tm << 7) * Ic;
    const float* Bt = B + (long long)e * ((long long)Cc * Ic) + ((long long)tn << 7) * Ic;

    float acc[4][4][4];
    #pragma unroll
    for (int i = 0; i < 4; i++)
        #pragma unroll
        for (int j = 0; j < 4; j++)
            #pragma unroll
            for (int r = 0; r < 4; r++) acc[i][j][r] = 0.f;

    auto ldst = [&](int s, int k0) {
        const uint32_t ab = sbase + (uint32_t)s * 32768u;
        const uint32_t bb = ab + 16384u;
        #pragma unroll
        for (int k = 0; k < 4; k++) {
            const int u = tid + (k << 8), r = u >> 3, c = u & 7;
            float4 v = *(const float4*)(At + (long long)r * Ic + k0 + (c << 2));
            v = make_float4(tf32r(v.x), tf32r(v.y), tf32r(v.z), tf32r(v.w));
            sts128(ab + ((uint32_t)r << 7) + ((uint32_t)(c ^ (r & 7)) << 4), v);
        }
        #pragma unroll
        for (int k = 0; k < 4; k++) {
            const int u = tid + (k << 8), r = u >> 3, c = u & 7;
            float4 v = *(const float4*)(Bt + (long long)r * Ic + k0 + (c << 2));
            v = make_float4(tf32r(v.x), tf32r(v.y), tf32r(v.z), tf32r(v.w));
            sts128(bb + ((uint32_t)r << 7) + ((uint32_t)(c ^ (r & 7)) << 4), v);
        }
    };

    const int rA = warpM * 64 + ((lane & 8) ? 8 : 0) + (lane & 7);
    const int chA = lane >> 4;
    const int rB = warpN * 32 + ((lane >> 4) << 3) + (lane & 7);
    const int chB = (lane >> 3) & 1;

    ldst(0, 0);
    __syncthreads();
    for (int kc = 0; kc < 8; kc++) {
        if (kc + 1 < 8) ldst((kc + 1) & 1, (kc + 1) << 5);
        const uint32_t ab = sbase + (uint32_t)(kc & 1) * 32768u;
        const uint32_t bb = ab + 16384u;
        #pragma unroll
        for (int k8 = 0; k8 < 4; k8++) {
            uint32_t aF[4][4], bF[2][4];
            #pragma unroll
            for (int mt = 0; mt < 4; mt++) {
                const int rr = rA + mt * 16;
                ldsm4(aF[mt], ab + ((uint32_t)rr << 7) +
                      ((uint32_t)(((k8 << 1) + chA) ^ (rr & 7)) << 4));
            }
            #pragma unroll
            for (int nt2 = 0; nt2 < 2; nt2++) {
                const int rr = rB + nt2 * 16;
                ldsm4(bF[nt2], bb + ((uint32_t)rr << 7) +
                      ((uint32_t)(((k8 << 1) + chB) ^ (rr & 7)) << 4));
            }
            #pragma unroll
            for (int mt = 0; mt < 4; mt++)
                #pragma unroll
                for (int nt = 0; nt < 4; nt++)
                    mma_tf32(acc[mt][nt], aF[mt], &bF[nt >> 1][(nt & 1) << 1]);
        }
        __syncthreads();
    }

    const int g = lane >> 2, t4 = lane & 3;
    #pragma unroll
    for (int mt = 0; mt < 4; mt++) {
        const int rg0 = (tm << 7) + warpM * 64 + mt * 16 + g;
        const int rg1 = rg0 + 8;
        const bool a0 = rg0 < ce, a1 = rg1 < ce;
        const int n0 = a0 ? idxp[e * Nc + rg0] : 0;
        const int n1 = a1 ? idxp[e * Nc + rg1] : 0;
        #pragma unroll
        for (int nt = 0; nt < 4; nt++) {
            const int col = (tn << 7) + warpN * 32 + nt * 8 + (t4 << 1);
            if (a0)
                *(float2*)&C[((long long)n0 * Ec + e) * Cc + col] =
                    make_float2(acc[mt][nt][0], acc[mt][nt][1]);
            if (a1)
                *(float2*)&C[((long long)n1 * Ec + e) * Cc + col] =
                    make_float2(acc[mt][nt][2], acc[mt][nt][3]);
        }
    }
}

__global__ void zero_cnt_k(int* cnt) { if (threadIdx.x < Ec) cnt[threadIdx.x] = 0; }

__global__ void __launch_bounds__(256) zero_eo_k(float4* __restrict__ p, long long n4)
{
    long long i = (long long)blockIdx.x * 256 + threadIdx.x;
    const long long stride = (long long)gridDim.x * 256;
    for (; i < n4; i += stride) p[i] = make_float4(0.f, 0.f, 0.f, 0.f);
}

__global__ void __launch_bounds__(256) transpose_k(
    const float* __restrict__ in, float* __restrict__ out, int R, int C)
{
    __shared__ float t[32][33];
    const long long zo = (long long)blockIdx.z * R * C;
    const int c0 = blockIdx.x << 5, r0 = blockIdx.y << 5;
    const int tx = threadIdx.x & 31, ty = threadIdx.x >> 5;
    #pragma unroll
    for (int k = 0; k < 32; k += 8)
        t[ty + k][tx] = in[zo + (long long)(r0 + ty + k) * C + c0 + tx];
    __syncthreads();
    #pragma unroll
    for (int k = 0; k < 32; k += 8)
        out[zo + (long long)(c0 + ty + k) * R + r0 + tx] = t[tx][ty + k];
}

// ------- fp32 SGEMM, f32x2, BK=16 double-buffered (exact, order-preserving) -------
__device__ __forceinline__ void sgemm_core2(
    const float* __restrict__ A, const float* __restrict__ B,
    int K, int Np, int brow, int bcol, ull acc2[8][4])
{
    __shared__ float As[2][16][128];
    __shared__ float Bs[2][16][128];
    const int tid = threadIdx.x;
    const int ar = tid & 127, ac = (tid >> 7) << 3;
    const int bk = tid >> 4, bcl = (tid & 15) << 3;
    const int tx = tid & 15, ty = tid >> 4;
    const float* Arow = A + (long long)(brow + ar) * K + ac;
    const float* Bbase = B + bcol + bcl + (long long)bk * Np;

    #pragma unroll
    for (int i = 0; i < 8; i++)
        #pragma unroll
        for (int p = 0; p < 4; p++) acc2[i][p] = 0ull;

    float4 la0, la1, lb0, lb1;
    auto ldg = [&](int k0) {
        la0 = *(const float4*)(Arow + k0);
        la1 = *(const float4*)(Arow + k0 + 4);
        lb0 = *(const float4*)(Bbase + (long long)k0 * Np);
        lb1 = *(const float4*)(Bbase + (long long)k0 * Np + 4);
    };
    auto sts = [&](int s) {
        As[s][ac+0][ar] = la0.x; As[s][ac+1][ar] = la0.y;
        As[s][ac+2][ar] = la0.z; As[s][ac+3][ar] = la0.w;
        As[s][ac+4][ar] = la1.x; As[s][ac+5][ar] = la1.y;
        As[s][ac+6][ar] = la1.z; As[s][ac+7][ar] = la1.w;
        *(float4*)&Bs[s][bk][bcl] = lb0;
        *(float4*)&Bs[s][bk][bcl + 4] = lb1;
    };

    const int NC16 = K >> 4;
    ldg(0); sts(0);
    __syncthreads();
    for (int kc = 0; kc < NC16; kc++) {
        if (kc + 1 < NC16) ldg((kc + 1) << 4);
        const int s = kc & 1;
        #pragma unroll
        for (int kk = 0; kk < 16; kk++) {
            float4 a0 = *(const float4*)&As[s][kk][ty << 3];
            float4 a1 = *(const float4*)&As[s][kk][(ty << 3) + 4];
            ulonglong2 b01 = *(const ulonglong2*)&Bs[s][kk][tx << 3];
            ulonglong2 b23 = *(const ulonglong2*)&Bs[s][kk][(tx << 3) + 4];
            ull a2[8];
            a2[0]=dup2(a0.x); a2[1]=dup2(a0.y); a2[2]=dup2(a0.z); a2[3]=dup2(a0.w);
            a2[4]=dup2(a1.x); a2[5]=dup2(a1.y); a2[6]=dup2(a1.z); a2[7]=dup2(a1.w);
            #pragma unroll
            for (int i = 0; i < 8; i++) {
                fma2(acc2[i][0], a2[i], b01.x);
                fma2(acc2[i][1], a2[i], b01.y);
                fma2(acc2[i][2], a2[i], b23.x);
                fma2(acc2[i][3], a2[i], b23.y);
            }
        }
        if (kc + 1 < NC16) sts((kc + 1) & 1);
        __syncthreads();
    }
}

__global__ void __launch_bounds__(256, 2) gemm_res_k(
    const float* __restrict__ A, const float* __restrict__ B, float* __restrict__ C,
    const float* __restrict__ res)
{
    const int brow = blockIdx.y << 7, bcol = blockIdx.x << 7;
    ull acc2[8][4];
    sgemm_core2(A, B, Cc, Cc, brow, bcol, acc2);
    const int tx = threadIdx.x & 15, ty = threadIdx.x >> 4;
    #pragma unroll
    for (int i = 0; i < 8; i++) {
        const int row = brow + (ty << 3) + i;
        #pragma unroll
        for (int p = 0; p < 4; p += 2) {
            const int col = bcol + (tx << 3) + (p << 1);
            float2 e0 = unpk(acc2[i][p]), e1 = unpk(acc2[i][p + 1]);
            float4 v = make_float4(e0.x, e0.y, e1.x, e1.y);
            float4 rv = *(const float4*)&res[(long long)row * Cc + col];
            v.x += rv.x; v.y += rv.y; v.z += rv.z; v.w += rv.w;
            *(float4*)&C[(long long)row * Cc + col] = v;
        }
    }
}

__global__ void __launch_bounds__(256, 2) gemm_qkv_k(
    const float* __restrict__ A,
    const float* __restrict__ b0, const float* __restrict__ b1, const float* __restrict__ b2,
    float* __restrict__ c0, float* __restrict__ c1, float* __restrict__ c2)
{
    const int z = blockIdx.z;
    const float* B = (z == 0) ? b0 : (z == 1) ? b1 : b2;
    float* C = (z == 0) ? c0 : (z == 1) ? c1 : c2;
    const int brow = blockIdx.y << 7, bcol = blockIdx.x << 7;
    ull acc2[8][4];
    sgemm_core2(A, B, Cc, Cc, brow, bcol, acc2);
    const int tx = threadIdx.x & 15, ty = threadIdx.x >> 4;
    #pragma unroll
    for (int i = 0; i < 8; i++) {
        const int row = brow + (ty << 3) + i;
        #pragma unroll
        for (int p = 0; p < 4; p += 2) {
            const int col = bcol + (tx << 3) + (p << 1);
            float2 e0 = unpk(acc2[i][p]), e1 = unpk(acc2[i][p + 1]);
            *(float4*)&C[(long long)row * Cc + col] = make_float4(e0.x, e0.y, e1.x, e1.y);
        }
    }
}

// ------- flash attention: paired q-tiles {qt, 15-qt} per block (R8-proven version) -------
#define AP 68
#define SM_ATTN2 (4 * 64 * AP * 4)
__global__ void __launch_bounds__(256) attn2_k(
    const float* __restrict__ Q, const float* __restrict__ K,
    const float* __restrict__ V, float* __restrict__ O)
{
    extern __shared__ float sm[];
    float* Qs = sm;
    float* Ks = sm + 64 * AP;
    float* Vs = sm + 2 * 64 * AP;
    float* Ps = sm + 3 * 64 * AP;
    const int h = blockIdx.y, b = blockIdx.z;
    const int tid = threadIdx.x;
    const int tx = tid & 15, ty = tid >> 4;
    const long long base = ((long long)b * Tc) * Cc + h * Dc;
    const int lr = tid >> 4;
    const int lc = (tid & 15) << 2;

    #pragma unroll
    for (int seg = 0; seg < 2; seg++) {
        const int qt = seg ? 15 - (int)blockIdx.x : (int)blockIdx.x;
        __syncthreads();
        #pragma unroll
        for (int rep = 0; rep < 4; rep++) {
            const int r = lr + (rep << 4);
            float4 v = *(const float4*)&Q[base + (long long)(qt * 64 + r) * Cc + lc];
            v.x *= 0.125f; v.y *= 0.125f; v.z *= 0.125f; v.w *= 0.125f;
            *(float4*)&Qs[r * AP + lc] = v;
        }

        ull acc2[4][2];
        float mi[4], li[4];
        #pragma unroll
        for (int i = 0; i < 4; i++) { acc2[i][0] = 0ull; acc2[i][1] = 0ull; mi[i] = -1e30f; li[i] = 0.f; }

        float4 kr[4], vr[4];
        #pragma unroll
        for (int rep = 0; rep < 4; rep++) {
            const int r = lr + (rep << 4);
            kr[rep] = *(const float4*)&K[base + (long long)r * Cc + lc];
            vr[rep] = *(const float4*)&V[base + (long long)r * Cc + lc];
        }

        for (int kt = 0; kt <= qt; kt++) {
            __syncthreads();
            #pragma unroll
            for (int rep = 0; rep < 4; rep++) {
                const int r = lr + (rep << 4);
                *(float4*)&Ks[r * AP + lc] = kr[rep];
                *(float4*)&Vs[r * AP + lc] = vr[rep];
            }
            __syncthreads();
            if (kt < qt) {
                #pragma unroll
                for (int rep = 0; rep < 4; rep++) {
                    const int r = lr + (rep << 4);
                    kr[rep] = *(const float4*)&K[base + (long long)((kt + 1) * 64 + r) * Cc + lc];
                    vr[rep] = *(const float4*)&V[base + (long long)((kt + 1) * 64 + r) * Cc + lc];
                }
            }
            ull s2[4][4];
            #pragma unroll
            for (int i = 0; i < 4; i++)
                #pragma unroll
                for (int j = 0; j < 4; j++) s2[i][j] = 0ull;
            #pragma unroll 4
            for (int d4 = 0; d4 < 16; d4++) {
                ulonglong2 la[4], lb[4];
                #pragma unroll
                for (int i = 0; i < 4; i++)
                    la[i] = *(const ulonglong2*)&Qs[((ty << 2) + i) * AP + (d4 << 2)];
                #pragma unroll
                for (int j = 0; j < 4; j++)
                    lb[j] = *(const ulonglong2*)&Ks[(tx + (j << 4)) * AP + (d4 << 2)];
                #pragma unroll
                for (int i = 0; i < 4; i++)
                    #pragma unroll
                    for (int j = 0; j < 4; j++) {
                        fma2(s2[i][j], la[i].x, lb[j].x);
                        fma2(s2[i][j], la[i].y, lb[j].y);
                    }
            }
            const bool diag = (kt == qt);
            #pragma unroll
            for (int i = 0; i < 4; i++) {
                float p[4];
                float mloc = -1e30f;
                #pragma unroll
                for (int j = 0; j < 4; j++) {
                    float2 u = unpk(s2[i][j]);
                    float sv = u.x + u.y;
                    if (diag && (tx + (j << 4)) > ((ty << 2) + i)) sv = -1e30f;
                    p[j] = sv;
                    mloc = fmaxf(mloc, sv);
                }
                mloc = fmaxf(mloc, __shfl_xor_sync(0xffffffffu, mloc, 1));
                mloc = fmaxf(mloc, __shfl_xor_sync(0xffffffffu, mloc, 2));
                mloc = fmaxf(mloc, __shfl_xor_sync(0xffffffffu, mloc, 4));
                mloc = fmaxf(mloc, __shfl_xor_sync(0xffffffffu, mloc, 8));
                const float mnew = fmaxf(mi[i], mloc);
                const float alpha = __expf(mi[i] - mnew);
                mi[i] = mnew;
                float ps = 0.f;
                #pragma unroll
                for (int j = 0; j < 4; j++) { p[j] = __expf(p[j] - mnew); ps += p[j]; }
                ps += __shfl_xor_sync(0xffffffffu, ps, 1);
                ps += __shfl_xor_sync(0xffffffffu, ps, 2);
                ps += __shfl_xor_sync(0xffffffffu, ps, 4);
                ps += __shfl_xor_sync(0xffffffffu, ps, 8);
                li[i] = li[i] * alpha + ps;
                const ull ad = dup2(alpha);
                acc2[i][0] = mul2(acc2[i][0], ad);
                acc2[i][1] = mul2(acc2[i][1], ad);
                float* pr = &Ps[((ty << 2) + i) * AP + tx];
                pr[0] = p[0]; pr[16] = p[1]; pr[32] = p[2]; pr[48] = p[3];
            }
            __syncthreads();
            #pragma unroll 4
            for (int j4 = 0; j4 < 16; j4++) {
                float4 pa[4];
                #pragma unroll
                for (int i = 0; i < 4; i++)
                    pa[i] = *(const float4*)&Ps[((ty << 2) + i) * AP + (j4 << 2)];
                #pragma unroll
                for (int jj = 0; jj < 4; jj++) {
                    const ulonglong2 vb = *(const ulonglong2*)&Vs[((j4 << 2) + jj) * AP + (tx << 2)];
                    #pragma unroll
                    for (int i = 0; i < 4; i++) {
                        const float* pf = (const float*)&pa[i];
                        const ull pd = dup2(pf[jj]);
                        fma2(acc2[i][0], pd, vb.x);
                        fma2(acc2[i][1], pd, vb.y);
                    }
                }
            }
        }
        #pragma unroll
        for (int i = 0; i < 4; i++) {
            const float inv = 1.f / li[i];
            float2 e0 = unpk(acc2[i][0]), e1 = unpk(acc2[i][1]);
            float4 v = make_float4(e0.x * inv, e0.y * inv, e1.x * inv, e1.y * inv);
            *(float4*)&O[base + (long long)(qt * 64 + (ty << 2) + i) * Cc + (tx << 2)] = v;
        }
    }
}

__global__ void __launch_bounds__(256) ln_k(
    const float* __restrict__ x, const float* __restrict__ g,
    const float* __restrict__ b, float* __restrict__ o)
{
    const int n = blockIdx.x, tid = threadIdx.x;
    const long long rb = (long long)n << 10;
    const int c = tid << 2;
    float4 v = *(const float4*)&x[rb + c];
    float s = v.x + v.y + v.z + v.w;
    float ss = v.x*v.x + v.y*v.y + v.z*v.z + v.w*v.w;
    #pragma unroll
    for (int off = 16; off; off >>= 1) {
        s  += __shfl_xor_sync(0xffffffffu, s, off);
        ss += __shfl_xor_sync(0xffffffffu, ss, off);
    }
    __shared__ float rs[8], rss[8], mv[2];
    const int w = tid >> 5, lane = tid & 31;
    if (!lane) { rs[w] = s; rss[w] = ss; }
    __syncthreads();
    if (tid == 0) {
        float S = 0, SS = 0;
        #pragma unroll
        for (int i = 0; i < 8; i++) { S += rs[i]; SS += rss[i]; }
        const float mean = S * (1.f/1024.f);
        const float var = SS * (1.f/1024.f) - mean * mean;
        mv[0] = mean; mv[1] = rsqrtf(var + 1e-5f);
    }
    __syncthreads();
    const float mean = mv[0], rstd = mv[1];
    float4 gg = *(const float4*)&g[c], bb = *(const float4*)&b[c];
    float4 ov;
    ov.x = (v.x-mean)*rstd*gg.x + bb.x; ov.y = (v.y-mean)*rstd*gg.y + bb.y;
    ov.z = (v.z-mean)*rstd*gg.z + bb.z; ov.w = (v.w-mean)*rstd*gg.w + bb.w;
    *(float4*)&o[rb + c] = ov;
}

__global__ void __launch_bounds__(256) colnorm_k(
    const float* __restrict__ sim, float* __restrict__ colinv)
{
    const int e = blockIdx.x, tid = threadIdx.x;
    float s = 0.f;
    for (int cc = tid; cc < 1024; cc += 256) {
        const float v = sim[cc * 16 + e];
        s = fmaf(v, v, s);
    }
    #pragma unroll
    for (int off = 16; off; off >>= 1) s += __shfl_xor_sync(0xffffffffu, s, off);
    __shared__ float rs[8];
    const int w = tid >> 5, lane = tid & 31;
    if (!lane) rs[w] = s;
    __syncthreads();
    if (tid == 0) {
        float S = 0;
        #pragma unroll
        for (int i = 0; i < 8; i++) S += rs[i];
        colinv[e] = rsqrtf(S);
    }
}

// ------- fused LN2 + routing scores + mask + kpt + expert compaction -------
__global__ void __launch_bounds__(256) lnscore_k(
    const float* __restrict__ x1, const float* __restrict__ g, const float* __restrict__ b,
    const float* __restrict__ sim, const float* __restrict__ thr,
    const float* __restrict__ colinv, float* __restrict__ oh2,
    float* __restrict__ oscores, float* __restrict__ okpt, float* __restrict__ maskb,
    int* __restrict__ cnt, int* __restrict__ idxp)
{
    const int n = blockIdx.x, tid = threadIdx.x;
    const long long rb = (long long)n << 10;
    const int c = tid << 2;
    const int w = tid >> 5, lane = tid & 31;

    float4 xv = *(const float4*)&x1[rb + c];
    {
        float s  = xv.x + xv.y + xv.z + xv.w;
        float ss = xv.x*xv.x + xv.y*xv.y + xv.z*xv.z + xv.w*xv.w;
        #pragma unroll
        for (int off = 16; off; off >>= 1) {
            s  += __shfl_xor_sync(0xffffffffu, s, off);
            ss += __shfl_xor_sync(0xffffffffu, ss, off);
        }
        __shared__ float rs0[8], rss0[8], mv[2];
        if (!lane) { rs0[w] = s; rss0[w] = ss; }
        __syncthreads();
        if (tid == 0) {
            float S = 0, SS = 0;
            #pragma unroll
            for (int i = 0; i < 8; i++) { S += rs0[i]; SS += rss0[i]; }
            const float mean = S * (1.f/1024.f);
            const float var = SS * (1.f/1024.f) - mean * mean;
            mv[0] = mean; mv[1] = rsqrtf(var + 1e-5f);
        }
        __syncthreads();
        const float mean = mv[0], rstd = mv[1];
        float4 gg = *(const float4*)&g[c], bb = *(const float4*)&b[c];
        xv.x = (xv.x-mean)*rstd*gg.x + bb.x; xv.y = (xv.y-mean)*rstd*gg.y + bb.y;
        xv.z = (xv.z-mean)*rstd*gg.z + bb.z; xv.w = (xv.w-mean)*rstd*gg.w + bb.w;
        *(float4*)&oh2[rb + c] = xv;
    }
    __syncthreads();

    float ss = xv.x*xv.x + xv.y*xv.y + xv.z*xv.z + xv.w*xv.w;
    float accd[16];
    #pragma unroll
    for (int e = 0; e < 16; e++) accd[e] = 0.f;
    const float hv[4] = {xv.x, xv.y, xv.z, xv.w};
    #pragma unroll
    for (int cc = 0; cc < 4; cc++) {
        const float* sr = &sim[(long long)(c + cc) << 4];
        #pragma unroll
        for (int e = 0; e < 16; e++) accd[e] = fmaf(hv[cc], sr[e], accd[e]);
    }
    #pragma unroll
    for (int off = 16; off; off >>= 1) ss += __shfl_xor_sync(0xffffffffu, ss, off);
    __shared__ float rs[8];
    __shared__ float red[16 * 8];
    __shared__ float smask[16];
    __shared__ float srn;
    if (!lane) rs[w] = ss;
    #pragma unroll
    for (int e = 0; e < 16; e++) {
        float t = accd[e];
        #pragma unroll
        for (int off = 16; off; off >>= 1) t += __shfl_xor_sync(0xffffffffu, t, off);
        if (!lane) red[e * 8 + w] = t;
    }
    __syncthreads();
    if (tid == 0) {
        float S = 0;
        #pragma unroll
        for (int i = 0; i < 8; i++) S += rs[i];
        srn = rsqrtf(S);
    }
    __syncthreads();
    if (tid < 16) {
        float sum = 0;
        #pragma unroll
        for (int i = 0; i < 8; i++) sum += red[tid * 8 + i];
        const float sc = sum * srn * colinv[tid];
        oscores[(n << 4) + tid] = sc;
        const float m = (sc > thr[0]) ? 1.f : 0.f;
        maskb[(n << 4) + tid] = m;
        smask[tid] = m;
        if (m != 0.f) {
            const int pos = atomicAdd(&cnt[tid], 1);
            idxp[tid * Nc + pos] = n;
        }
    }
    __syncthreads();
    if (tid == 0) {
        float kc = 0;
        #pragma unroll
        for (int e = 0; e < 16; e++) kc += smask[e];
        okpt[n] = kc;
    }
}

__global__ void __launch_bounds__(256) final_k(
    const float* __restrict__ x1, const float* __restrict__ eo,
    const float* __restrict__ maskb, float* __restrict__ ox)
{
    const int n = blockIdx.x, tid = threadIdx.x;
    __shared__ float mk[16];
    if (tid < 16) mk[tid] = maskb[(n << 4) + tid];
    __syncthreads();
    const int c = tid << 2;
    const long long rb = (long long)n << 10;
    float4 v = *(const float4*)&x1[rb + c];
    #pragma unroll
    for (int e = 0; e < 16; e++) {
        if (mk[e] != 0.f) {
            const float4 wv = *(const float4*)&eo[(((long long)(n * 16 + e)) << 10) + c];
            v.x += wv.x; v.y += wv.y; v.z += wv.z; v.w += wv.w;
        }
    }
    *(float4*)&ox[rb + c] = v;
}

extern "C" void kernel_launch(void* const* d_in, const int* in_sizes, int n_in,
                              void* d_out, int out_size)
{
    (void)in_sizes; (void)n_in;
    const float* x    = (const float*)d_in[0];
    const float* ln1g = (const float*)d_in[1];
    const float* ln1b = (const float*)d_in[2];
    const float* ln2g = (const float*)d_in[3];
    const float* ln2b = (const float*)d_in[4];
    const float* wq   = (const float*)d_in[5];
    const float* wk   = (const float*)d_in[6];
    const float* wv   = (const float*)d_in[7];
    const float* wo   = (const float*)d_in[8];
    const float* sim  = (const float*)d_in[9];
    const float* thr  = (const float*)d_in[10];
    const float* w1   = (const float*)d_in[11];
    const float* w2   = (const float*)d_in[12];

    float *ph, *pq, *pk, *pv, *pao, *px1, *pmid, *pw1t, *pw2t, *peos, *pmask, *pcol, *pssc, *pkpt;
    int *pcnt, *pidx;
    cudaGetSymbolAddress((void**)&ph, g_h);
    cudaGetSymbolAddress((void**)&pq, g_q);
    cudaGetSymbolAddress((void**)&pk, g_k);
    cudaGetSymbolAddress((void**)&pv, g_v);
    cudaGetSymbolAddress((void**)&pao, g_ao);
    cudaGetSymbolAddress((void**)&px1, g_x1);
    cudaGetSymbolAddress((void**)&pmid, g_mid);
    cudaGetSymbolAddress((void**)&pw1t, g_w1t);
    cudaGetSymbolAddress((void**)&pw2t, g_w2t);
    cudaGetSymbolAddress((void**)&peos, g_eo_scr);
    cudaGetSymbolAddress((void**)&pmask, g_mask);
    cudaGetSymbolAddress((void**)&pcol, g_colinv);
    cudaGetSymbolAddress((void**)&pssc, g_scores_scr);
    cudaGetSymbolAddress((void**)&pkpt, g_kpt_scr);
    cudaGetSymbolAddress((void**)&pcnt, g_cnt);
    cudaGetSymbolAddress((void**)&pidx, g_idx);

    const long long XN  = (long long)Nc * Cc;
    const long long SCN = (long long)Nc * Ec;
    const long long EON = (long long)Nc * Ec * Cc;
    const bool full = ((long long)out_size >= XN + SCN + EON + Nc);
    float* out   = (float*)d_out;
    float* o_x   = out;
    float* o_sc  = full ? out + XN : pssc;
    float* o_eo  = full ? out + XN + SCN : peos;
    float* o_kpt = full ? out + XN + SCN + EON : pkpt;

    cudaFuncSetAttribute(attn2_k, cudaFuncAttributeMaxDynamicSharedMemorySize, SM_ATTN2);
    cudaFuncSetAttribute(moe_g1_k, cudaFuncAttributeMaxDynamicSharedMemorySize, MOE_SMEM);
    cudaFuncSetAttribute(moe_s2_k, cudaFuncAttributeMaxDynamicSharedMemorySize, MOE_SMEM);

    // ---- one side stream (same footprint as the passing R7/R8/R10 pattern) ----
    cudaStream_t s2;
    cudaStreamCreateWithFlags(&s2, cudaStreamNonBlocking);
    cudaEvent_t ev1, evPrep, evScore, evMoe;
    cudaEventCreateWithFlags(&ev1, cudaEventDisableTiming);
    cudaEventCreateWithFlags(&evPrep, cudaEventDisableTiming);
    cudaEventCreateWithFlags(&evScore, cudaEventDisableTiming);
    cudaEventCreateWithFlags(&evMoe, cudaEventDisableTiming);

    cudaEventRecord(ev1, 0);
    cudaStreamWaitEvent(s2, ev1, 0);
    zero_eo_k<<<2048, 256, 0, s2>>>((float4*)o_eo, EON / 4);
    zero_cnt_k<<<1, 32, 0, s2>>>(pcnt);
    transpose_k<<<dim3(8, 32, 16), 256, 0, s2>>>(w1, pw1t, Cc, Ic);
    transpose_k<<<dim3(32, 8, 16), 256, 0, s2>>>(w2, pw2t, Ic, Cc);
    colnorm_k<<<16, 256, 0, s2>>>(sim, pcol);
    cudaEventRecord(evPrep, s2);

    // ---- main chain ----
    ln_k<<<Nc, 256>>>(x, ln1g, ln1b, ph);
    gemm_qkv_k<<<dim3(8, 16, 3), 256>>>(ph, wq, wk, wv, pq, pk, pv);
    attn2_k<<<dim3(8, Hc, Bc), 256, SM_ATTN2>>>(pq, pk, pv, pao);
    gemm_res_k<<<dim3(8, 16, 1), 256>>>(pao, wo, px1, x);

    cudaStreamWaitEvent(0, evPrep, 0);
    lnscore_k<<<Nc, 256>>>(px1, ln2g, ln2b, sim, thr, pcol, ph,
                           o_sc, o_kpt, pmask, pcnt, pidx);
    cudaEventRecord(evScore, 0);

    // ---- 2-way split MoE: experts 0-7 on default stream, 8-15 on s2 ----
    cudaStreamWaitEvent(s2, evScore, 0);
    moe_g1_k<<<dim3(2, 16, 8), 256, MOE_SMEM, s2>>>(ph, pw1t, pmid, pidx, pcnt, 8);
    moe_s2_k<<<dim3(8, 16, 8), 256, MOE_SMEM, s2>>>(pmid, pw2t, o_eo, pidx, pcnt, 8);
    cudaEventRecord(evMoe, s2);

    moe_g1_k<<<dim3(2, 16, 8), 256, MOE_SMEM>>>(ph, pw1t, pmid, pidx, pcnt, 0);
    moe_s2_k<<<dim3(8, 16, 8), 256, MOE_SMEM>>>(pmid, pw2t, o_eo, pidx, pcnt, 0);

    cudaStreamWaitEvent(0, evMoe, 0);
    final_k<<<Nc, 256>>>(px1, o_eo, pmask, o_x);
}

// round 12
// speedup vs baseline: 1.0302x; 1.0034x over previous
#include <cuda_runtime.h>
#include <math.h>
#include <stdint.h>

#define Bc 2
#define Tc 1024
#define Cc 1024
#define Hc 16
#define Dc 64
#define Ec 16
#define Ic 256
#define Nc (Bc*Tc)

typedef unsigned long long ull;

__device__ float g_h  [Nc*Cc];
__device__ float g_q  [Nc*Cc];
__device__ float g_k  [Nc*Cc];
__device__ float g_v  [Nc*Cc];
__device__ float g_ao [Nc*Cc];
__device__ float g_x1 [Nc*Cc];
__device__ float g_mid[(long long)Ec*Nc*Ic];
__device__ float g_w1t[(long long)Ec*Ic*Cc];
__device__ float g_w2t[(long long)Ec*Cc*Ic];
__device__ float g_eo_scr[(long long)Nc*Ec*Cc];
__device__ float g_mask[Nc*Ec];
__device__ float g_colinv[Ec];
__device__ float g_scores_scr[Nc*Ec];
__device__ float g_kpt_scr[Nc];
__device__ int   g_cnt[Ec];
__device__ int   g_idx[Ec*Nc];

__device__ __forceinline__ float gelu_f(float x) {
    return 0.5f * x * (1.0f + erff(x * 0.70710678118654752440f));
}
__device__ __forceinline__ uint32_t smem_u32(const void* p) {
    uint32_t a;
    asm("{ .reg .u64 t; cvta.to.shared.u64 t, %1; cvt.u32.u64 %0, t; }" : "=r"(a) : "l"(p));
    return a;
}
__device__ __forceinline__ float tf32r(float x) {
    float o; asm("cvt.rna.tf32.f32 %0, %1;" : "=f"(o) : "f"(x)); return o;
}
__device__ __forceinline__ void sts128(uint32_t a, float4 v) {
    asm volatile("st.shared.v4.b32 [%0], {%1,%2,%3,%4};" ::
                 "r"(a), "f"(v.x), "f"(v.y), "f"(v.z), "f"(v.w) : "memory");
}
__device__ __forceinline__ void ldsm4(uint32_t (&d)[4], uint32_t addr) {
    asm volatile("ldmatrix.sync.aligned.m8n8.x4.shared.b16 {%0,%1,%2,%3}, [%4];"
                 : "=r"(d[0]), "=r"(d[1]), "=r"(d[2]), "=r"(d[3]) : "r"(addr));
}
__device__ __forceinline__ void mma_tf32(float (&c)[4], const uint32_t (&a)[4], const uint32_t* b) {
    asm volatile("mma.sync.aligned.m16n8k8.row.col.f32.tf32.tf32.f32 "
                 "{%0,%1,%2,%3}, {%4,%5,%6,%7}, {%8,%9}, {%0,%1,%2,%3};"
                 : "+f"(c[0]), "+f"(c[1]), "+f"(c[2]), "+f"(c[3])
                 : "r"(a[0]), "r"(a[1]), "r"(a[2]), "r"(a[3]), "r"(b[0]), "r"(b[1]));
}
__device__ __forceinline__ ull dup2(float x) {
    ull r; asm("mov.b64 %0, {%1,%1};" : "=l"(r) : "f"(x)); return r;
}
__device__ __forceinline__ void fma2(ull &c, ull a, ull b) {
    asm("fma.rn.f32x2 %0, %1, %2, %0;" : "+l"(c) : "l"(a), "l"(b));
}
__device__ __forceinline__ ull mul2(ull a, ull b) {
    ull d; asm("mul.rn.f32x2 %0, %1, %2;" : "=l"(d) : "l"(a), "l"(b)); return d;
}
__device__ __forceinline__ float2 unpk(ull v) {
    float2 f; asm("mov.b64 {%0,%1}, %2;" : "=f"(f.x), "=f"(f.y) : "l"(v)); return f;
}

// ================= MoE tf32 MMA (gathered / scattered) =================
#define MOE_SMEM 65536

__global__ void __launch_bounds__(256) moe_g1_k(
    const float* __restrict__ A, const float* __restrict__ B, float* __restrict__ C,
    const int* __restrict__ idxp, const int* __restrict__ cntp)
{
    extern __shared__ float dsm[];
    const int e = blockIdx.z, tm = blockIdx.y, tn = blockIdx.x;
    const int ce = cntp[e];
    if ((tm << 7) >= ce) return;
    const int tid = threadIdx.x, wid = tid >> 5, lane = tid & 31;
    const int warpM = wid >> 2, warpN = wid & 3;
    const uint32_t sbase = smem_u32(dsm);

    int srcA[4];
    #pragma unroll
    for (int k = 0; k < 4; k++) {
        const int r = (tid + (k << 8)) >> 3;
        int gr = (tm << 7) + r;
        if (gr >= ce) gr = ce - 1;
        srcA[k] = idxp[e * Nc + gr];
    }
    const float* Bt = B + (long long)e * ((long long)Ic * Cc) + ((long long)tn << 7) * Cc;

    float acc[4][4][4];
    #pragma unroll
    for (int i = 0; i < 4; i++)
        #pragma unroll
        for (int j = 0; j < 4; j++)
            #pragma unroll
            for (int r = 0; r < 4; r++) acc[i][j][r] = 0.f;

    auto ldst = [&](int s, int k0) {
        const uint32_t ab = sbase + (uint32_t)s * 32768u;
        const uint32_t bb = ab + 16384u;
        #pragma unroll
        for (int k = 0; k < 4; k++) {
            const int u = tid + (k << 8), r = u >> 3, c = u & 7;
            float4 v = *(const float4*)(A + (long long)srcA[k] * Cc + k0 + (c << 2));
            v = make_float4(tf32r(v.x), tf32r(v.y), tf32r(v.z), tf32r(v.w));
            sts128(ab + ((uint32_t)r << 7) + ((uint32_t)(c ^ (r & 7)) << 4), v);
        }
        #pragma unroll
        for (int k = 0; k < 4; k++) {
            const int u = tid + (k << 8), r = u >> 3, c = u & 7;
            float4 v = *(const float4*)(Bt + (long long)r * Cc + k0 + (c << 2));
            v = make_float4(tf32r(v.x), tf32r(v.y), tf32r(v.z), tf32r(v.w));
            sts128(bb + ((uint32_t)r << 7) + ((uint32_t)(c ^ (r & 7)) << 4), v);
        }
    };

    const int rA = warpM * 64 + ((lane & 8) ? 8 : 0) + (lane & 7);
    const int chA = lane >> 4;
    const int rB = warpN * 32 + ((lane >> 4) << 3) + (lane & 7);
    const int chB = (lane >> 3) & 1;

    ldst(0, 0);
    __syncthreads();
    for (int kc = 0; kc < 32; kc++) {
        if (kc + 1 < 32) ldst((kc + 1) & 1, (kc + 1) << 5);
        const uint32_t ab = sbase + (uint32_t)(kc & 1) * 32768u;
        const uint32_t bb = ab + 16384u;
        #pragma unroll
        for (int k8 = 0; k8 < 4; k8++) {
            uint32_t aF[4][4], bF[2][4];
            #pragma unroll
            for (int mt = 0; mt < 4; mt++) {
                const int rr = rA + mt * 16;
                ldsm4(aF[mt], ab + ((uint32_t)rr << 7) +
                      ((uint32_t)(((k8 << 1) + chA) ^ (rr & 7)) << 4));
            }
            #pragma unroll
            for (int nt2 = 0; nt2 < 2; nt2++) {
                const int rr = rB + nt2 * 16;
                ldsm4(bF[nt2], bb + ((uint32_t)rr << 7) +
                      ((uint32_t)(((k8 << 1) + chB) ^ (rr & 7)) << 4));
            }
            #pragma unroll
            for (int mt = 0; mt < 4; mt++)
                #pragma unroll
                for (int nt = 0; nt < 4; nt++)
                    mma_tf32(acc[mt][nt], aF[mt], &bF[nt >> 1][(nt & 1) << 1]);
        }
        __syncthreads();
    }

    float* Ct = C + (long long)e * ((long long)Nc * Ic);
    const int g = lane >> 2, t4 = lane & 3;
    #pragma unroll
    for (int mt = 0; mt < 4; mt++) {
        const int row0 = (tm << 7) + warpM * 64 + mt * 16 + g;
        #pragma unroll
        for (int nt = 0; nt < 4; nt++) {
            const int col = (tn << 7) + warpN * 32 + nt * 8 + (t4 << 1);
            float2 v0 = make_float2(gelu_f(acc[mt][nt][0]), gelu_f(acc[mt][nt][1]));
            float2 v1 = make_float2(gelu_f(acc[mt][nt][2]), gelu_f(acc[mt][nt][3]));
            *(float2*)&Ct[(long long)row0 * Ic + col] = v0;
            *(float2*)&Ct[(long long)(row0 + 8) * Ic + col] = v1;
        }
    }
}

__global__ void __launch_bounds__(256) moe_s2_k(
    const float* __restrict__ A, const float* __restrict__ B, float* __restrict__ C,
    const int* __restrict__ idxp, const int* __restrict__ cntp)
{
    extern __shared__ float dsm[];
    const int e = blockIdx.z, tm = blockIdx.y, tn = blockIdx.x;
    const int ce = cntp[e];
    if ((tm << 7) >= ce) return;
    const int tid = threadIdx.x, wid = tid >> 5, lane = tid & 31;
    const int warpM = wid >> 2, warpN = wid & 3;
    const uint32_t sbase = smem_u32(dsm);

    const float* At = A + (long long)e * ((long long)Nc * Ic) + ((long long)tm << 7) * Ic;
    const float* Bt = B + (long long)e * ((long long)Cc * Ic) + ((long long)tn << 7) * Ic;

    float acc[4][4][4];
    #pragma unroll
    for (int i = 0; i < 4; i++)
        #pragma unroll
        for (int j = 0; j < 4; j++)
            #pragma unroll
            for (int r = 0; r < 4; r++) acc[i][j][r] = 0.f;

    auto ldst = [&](int s, int k0) {
        const uint32_t ab = sbase + (uint32_t)s * 32768u;
        const uint32_t bb = ab + 16384u;
        #pragma unroll
        for (int k = 0; k < 4; k++) {
            const int u = tid + (k << 8), r = u >> 3, c = u & 7;
            float4 v = *(const float4*)(At + (long long)r * Ic + k0 + (c << 2));
            v = make_float4(tf32r(v.x), tf32r(v.y), tf32r(v.z), tf32r(v.w));
            sts128(ab + ((uint32_t)r << 7) + ((uint32_t)(c ^ (r & 7)) << 4), v);
        }
        #pragma unroll
        for (int k = 0; k < 4; k++) {
            const int u = tid + (k << 8), r = u >> 3, c = u & 7;
            float4 v = *(const float4*)(Bt + (long long)r * Ic + k0 + (c << 2));
            v = make_float4(tf32r(v.x), tf32r(v.y), tf32r(v.z), tf32r(v.w));
            sts128(bb + ((uint32_t)r << 7) + ((uint32_t)(c ^ (r & 7)) << 4), v);
        }
    };

    const int rA = warpM * 64 + ((lane & 8) ? 8 : 0) + (lane & 7);
    const int chA = lane >> 4;
    const int rB = warpN * 32 + ((lane >> 4) << 3) + (lane & 7);
    const int chB = (lane >> 3) & 1;

    ldst(0, 0);
    __syncthreads();
    for (int kc = 0; kc < 8; kc++) {
        if (kc + 1 < 8) ldst((kc + 1) & 1, (kc + 1) << 5);
        const uint32_t ab = sbase + (uint32_t)(kc & 1) * 32768u;
        const uint32_t bb = ab + 16384u;
        #pragma unroll
        for (int k8 = 0; k8 < 4; k8++) {
            uint32_t aF[4][4], bF[2][4];
            #pragma unroll
            for (int mt = 0; mt < 4; mt++) {
                const int rr = rA + mt * 16;
                ldsm4(aF[mt], ab + ((uint32_t)rr << 7) +
                      ((uint32_t)(((k8 << 1) + chA) ^ (rr & 7)) << 4));
            }
            #pragma unroll
            for (int nt2 = 0; nt2 < 2; nt2++) {
                const int rr = rB + nt2 * 16;
                ldsm4(bF[nt2], bb + ((uint32_t)rr << 7) +
                      ((uint32_t)(((k8 << 1) + chB) ^ (rr & 7)) << 4));
            }
            #pragma unroll
            for (int mt = 0; mt < 4; mt++)
                #pragma unroll
                for (int nt = 0; nt < 4; nt++)
                    mma_tf32(acc[mt][nt], aF[mt], &bF[nt >> 1][(nt & 1) << 1]);
        }
        __syncthreads();
    }

    const int g = lane >> 2, t4 = lane & 3;
    #pragma unroll
    for (int mt = 0; mt < 4; mt++) {
        const int rg0 = (tm << 7) + warpM * 64 + mt * 16 + g;
        const int rg1 = rg0 + 8;
        const bool a0 = rg0 < ce, a1 = rg1 < ce;
        const int n0 = a0 ? idxp[e * Nc + rg0] : 0;
        const int n1 = a1 ? idxp[e * Nc + rg1] : 0;
        #pragma unroll
        for (int nt = 0; nt < 4; nt++) {
            const int col = (tn << 7) + warpN * 32 + nt * 8 + (t4 << 1);
            if (a0)
                *(float2*)&C[((long long)n0 * Ec + e) * Cc + col] =
                    make_float2(acc[mt][nt][0], acc[mt][nt][1]);
            if (a1)
                *(float2*)&C[((long long)n1 * Ec + e) * Cc + col] =
                    make_float2(acc[mt][nt][2], acc[mt][nt][3]);
        }
    }
}

__global__ void zero_cnt_k(int* cnt) { if (threadIdx.x < Ec) cnt[threadIdx.x] = 0; }

__global__ void __launch_bounds__(256) zero_eo_k(float4* __restrict__ p, long long n4)
{
    long long i = (long long)blockIdx.x * 256 + threadIdx.x;
    const long long stride = (long long)gridDim.x * 256;
    for (; i < n4; i += stride) p[i] = make_float4(0.f, 0.f, 0.f, 0.f);
}

__global__ void __launch_bounds__(256) transpose_k(
    const float* __restrict__ in, float* __restrict__ out, int R, int C)
{
    __shared__ float t[32][33];
    const long long zo = (long long)blockIdx.z * R * C;
    const int c0 = blockIdx.x << 5, r0 = blockIdx.y << 5;
    const int tx = threadIdx.x & 31, ty = threadIdx.x >> 5;
    #pragma unroll
    for (int k = 0; k < 32; k += 8)
        t[ty + k][tx] = in[zo + (long long)(r0 + ty + k) * C + c0 + tx];
    __syncthreads();
    #pragma unroll
    for (int k = 0; k < 32; k += 8)
        out[zo + (long long)(c0 + ty + k) * R + r0 + tx] = t[tx][ty + k];
}

// ------- fp32 SGEMM, f32x2, BK=16 double-buffered (exact, order-preserving) -------
__device__ __forceinline__ void sgemm_core2(
    const float* __restrict__ A, const float* __restrict__ B,
    int K, int Np, int brow, int bcol, ull acc2[8][4])
{
    __shared__ float As[2][16][128];
    __shared__ float Bs[2][16][128];
    const int tid = threadIdx.x;
    const int ar = tid & 127, ac = (tid >> 7) << 3;
    const int bk = tid >> 4, bcl = (tid & 15) << 3;
    const int tx = tid & 15, ty = tid >> 4;
    const float* Arow = A + (long long)(brow + ar) * K + ac;
    const float* Bbase = B + bcol + bcl + (long long)bk * Np;

    #pragma unroll
    for (int i = 0; i < 8; i++)
        #pragma unroll
        for (int p = 0; p < 4; p++) acc2[i][p] = 0ull;

    float4 la0, la1, lb0, lb1;
    auto ldg = [&](int k0) {
        la0 = *(const float4*)(Arow + k0);
        la1 = *(const float4*)(Arow + k0 + 4);
        lb0 = *(const float4*)(Bbase + (long long)k0 * Np);
        lb1 = *(const float4*)(Bbase + (long long)k0 * Np + 4);
    };
    auto sts = [&](int s) {
        As[s][ac+0][ar] = la0.x; As[s][ac+1][ar] = la0.y;
        As[s][ac+2][ar] = la0.z; As[s][ac+3][ar] = la0.w;
        As[s][ac+4][ar] = la1.x; As[s][ac+5][ar] = la1.y;
        As[s][ac+6][ar] = la1.z; As[s][ac+7][ar] = la1.w;
        *(float4*)&Bs[s][bk][bcl] = lb0;
        *(float4*)&Bs[s][bk][bcl + 4] = lb1;
    };

    const int NC16 = K >> 4;
    ldg(0); sts(0);
    __syncthreads();
    for (int kc = 0; kc < NC16; kc++) {
        if (kc + 1 < NC16) ldg((kc + 1) << 4);
        const int s = kc & 1;
        #pragma unroll
        for (int kk = 0; kk < 16; kk++) {
            float4 a0 = *(const float4*)&As[s][kk][ty << 3];
            float4 a1 = *(const float4*)&As[s][kk][(ty << 3) + 4];
            ulonglong2 b01 = *(const ulonglong2*)&Bs[s][kk][tx << 3];
            ulonglong2 b23 = *(const ulonglong2*)&Bs[s][kk][(tx << 3) + 4];
            ull a2[8];
            a2[0]=dup2(a0.x); a2[1]=dup2(a0.y); a2[2]=dup2(a0.z); a2[3]=dup2(a0.w);
            a2[4]=dup2(a1.x); a2[5]=dup2(a1.y); a2[6]=dup2(a1.z); a2[7]=dup2(a1.w);
            #pragma unroll
            for (int i = 0; i < 8; i++) {
                fma2(acc2[i][0], a2[i], b01.x);
                fma2(acc2[i][1], a2[i], b01.y);
                fma2(acc2[i][2], a2[i], b23.x);
                fma2(acc2[i][3], a2[i], b23.y);
            }
        }
        if (kc + 1 < NC16) sts((kc + 1) & 1);
        __syncthreads();
    }
}

__global__ void __launch_bounds__(256, 2) gemm_res_k(
    const float* __restrict__ A, const float* __restrict__ B, float* __restrict__ C,
    const float* __restrict__ res)
{
    const int brow = blockIdx.y << 7, bcol = blockIdx.x << 7;
    ull acc2[8][4];
    sgemm_core2(A, B, Cc, Cc, brow, bcol, acc2);
    const int tx = threadIdx.x & 15, ty = threadIdx.x >> 4;
    #pragma unroll
    for (int i = 0; i < 8; i++) {
        const int row = brow + (ty << 3) + i;
        #pragma unroll
        for (int p = 0; p < 4; p += 2) {
            const int col = bcol + (tx << 3) + (p << 1);
            float2 e0 = unpk(acc2[i][p]), e1 = unpk(acc2[i][p + 1]);
            float4 v = make_float4(e0.x, e0.y, e1.x, e1.y);
            float4 rv = *(const float4*)&res[(long long)row * Cc + col];
            v.x += rv.x; v.y += rv.y; v.z += rv.z; v.w += rv.w;
            *(float4*)&C[(long long)row * Cc + col] = v;
        }
    }
}

__global__ void __launch_bounds__(256, 2) gemm_qkv_k(
    const float* __restrict__ A,
    const float* __restrict__ b0, const float* __restrict__ b1, const float* __restrict__ b2,
    float* __restrict__ c0, float* __restrict__ c1, float* __restrict__ c2)
{
    const int z = blockIdx.z;
    const float* B = (z == 0) ? b0 : (z == 1) ? b1 : b2;
    float* C = (z == 0) ? c0 : (z == 1) ? c1 : c2;
    const int brow = blockIdx.y << 7, bcol = blockIdx.x << 7;
    ull acc2[8][4];
    sgemm_core2(A, B, Cc, Cc, brow, bcol, acc2);
    const int tx = threadIdx.x & 15, ty = threadIdx.x >> 4;
    #pragma unroll
    for (int i = 0; i < 8; i++) {
        const int row = brow + (ty << 3) + i;
        #pragma unroll
        for (int p = 0; p < 4; p += 2) {
            const int col = bcol + (tx << 3) + (p << 1);
            float2 e0 = unpk(acc2[i][p]), e1 = unpk(acc2[i][p + 1]);
            *(float4*)&C[(long long)row * Cc + col] = make_float4(e0.x, e0.y, e1.x, e1.y);
        }
    }
}

// ------- flash attention: paired q-tiles, phase-batched exp2 softmax -------
#define AP 68
#define SM_ATTN2 (4 * 64 * AP * 4)
#define QSCALE 0.18033688011112042592f   /* 0.125 * log2(e) */
__global__ void __launch_bounds__(256) attn2_k(
    const float* __restrict__ Q, const float* __restrict__ K,
    const float* __restrict__ V, float* __restrict__ O)
{
    extern __shared__ float sm[];
    float* Qs = sm;
    float* Ks = sm + 64 * AP;
    float* Vs = sm + 2 * 64 * AP;
    float* Ps = sm + 3 * 64 * AP;
    const int h = blockIdx.y, b = blockIdx.z;
    const int tid = threadIdx.x;
    const int tx = tid & 15, ty = tid >> 4;
    const long long base = ((long long)b * Tc) * Cc + h * Dc;
    const int lr = tid >> 4;
    const int lc = (tid & 15) << 2;

    #pragma unroll
    for (int seg = 0; seg < 2; seg++) {
        const int qt = seg ? 15 - (int)blockIdx.x : (int)blockIdx.x;
        __syncthreads();
        #pragma unroll
        for (int rep = 0; rep < 4; rep++) {
            const int r = lr + (rep << 4);
            float4 v = *(const float4*)&Q[base + (long long)(qt * 64 + r) * Cc + lc];
            v.x *= QSCALE; v.y *= QSCALE; v.z *= QSCALE; v.w *= QSCALE;
            *(float4*)&Qs[r * AP + lc] = v;
        }

        ull acc2[4][2];
        float mi[4], li[4];
        #pragma unroll
        for (int i = 0; i < 4; i++) { acc2[i][0] = 0ull; acc2[i][1] = 0ull; mi[i] = -1e30f; li[i] = 0.f; }

        float4 kr[4], vr[4];
        #pragma unroll
        for (int rep = 0; rep < 4; rep++) {
            const int r = lr + (rep << 4);
            kr[rep] = *(const float4*)&K[base + (long long)r * Cc + lc];
            vr[rep] = *(const float4*)&V[base + (long long)r * Cc + lc];
        }

        for (int kt = 0; kt <= qt; kt++) {
            __syncthreads();
            #pragma unroll
            for (int rep = 0; rep < 4; rep++) {
                const int r = lr + (rep << 4);
                *(float4*)&Ks[r * AP + lc] = kr[rep];
                *(float4*)&Vs[r * AP + lc] = vr[rep];
            }
            __syncthreads();
            if (kt < qt) {
                #pragma unroll
                for (int rep = 0; rep < 4; rep++) {
                    const int r = lr + (rep << 4);
                    kr[rep] = *(const float4*)&K[base + (long long)((kt + 1) * 64 + r) * Cc + lc];
                    vr[rep] = *(const float4*)&V[base + (long long)((kt + 1) * 64 + r) * Cc + lc];
                }
            }
            ull s2[4][4];
            #pragma unroll
            for (int i = 0; i < 4; i++)
                #pragma unroll
                for (int j = 0; j < 4; j++) s2[i][j] = 0ull;
            #pragma unroll 4
            for (int d4 = 0; d4 < 16; d4++) {
                ulonglong2 la[4], lb[4];
                #pragma unroll
                for (int i = 0; i < 4; i++)
                    la[i] = *(const ulonglong2*)&Qs[((ty << 2) + i) * AP + (d4 << 2)];
                #pragma unroll
                for (int j = 0; j < 4; j++)
                    lb[j] = *(const ulonglong2*)&Ks[(tx + (j << 4)) * AP + (d4 << 2)];
                #pragma unroll
                for (int i = 0; i < 4; i++)
                    #pragma unroll
                    for (int j = 0; j < 4; j++) {
                        fma2(s2[i][j], la[i].x, lb[j].x);
                        fma2(s2[i][j], la[i].y, lb[j].y);
                    }
            }
            // ---- phase-batched online softmax (log2 domain) ----
            const bool diag = (kt == qt);
            float p[4][4], mloc[4];
            #pragma unroll
            for (int i = 0; i < 4; i++) {
                mloc[i] = -1e30f;
                #pragma unroll
                for (int j = 0; j < 4; j++) {
                    float2 u = unpk(s2[i][j]);
                    float sv = u.x + u.y;
                    if (diag && (tx + (j << 4)) > ((ty << 2) + i)) sv = -1e30f;
                    p[i][j] = sv;
                    mloc[i] = fmaxf(mloc[i], sv);
                }
            }
            #pragma unroll
            for (int st = 1; st <= 8; st <<= 1)
                #pragma unroll
                for (int i = 0; i < 4; i++)
                    mloc[i] = fmaxf(mloc[i], __shfl_xor_sync(0xffffffffu, mloc[i], st));
            float alpha[4], ps[4];
            #pragma unroll
            for (int i = 0; i < 4; i++) {
                const float mnew = fmaxf(mi[i], mloc[i]);
                alpha[i] = exp2f(mi[i] - mnew);
                mi[i] = mnew;
                ps[i] = 0.f;
                #pragma unroll
                for (int j = 0; j < 4; j++) {
                    p[i][j] = exp2f(p[i][j] - mnew);
                    ps[i] += p[i][j];
                }
            }
            #pragma unroll
            for (int st = 1; st <= 8; st <<= 1)
                #pragma unroll
                for (int i = 0; i < 4; i++)
                    ps[i] += __shfl_xor_sync(0xffffffffu, ps[i], st);
            #pragma unroll
            for (int i = 0; i < 4; i++) {
                li[i] = li[i] * alpha[i] + ps[i];
                const ull ad = dup2(alpha[i]);
                acc2[i][0] = mul2(acc2[i][0], ad);
                acc2[i][1] = mul2(acc2[i][1], ad);
                float* pr = &Ps[((ty << 2) + i) * AP + tx];
                pr[0] = p[i][0]; pr[16] = p[i][1]; pr[32] = p[i][2]; pr[48] = p[i][3];
            }
            __syncthreads();
            #pragma unroll 4
            for (int j4 = 0; j4 < 16; j4++) {
                float4 pa[4];
                #pragma unroll
                for (int i = 0; i < 4; i++)
                    pa[i] = *(const float4*)&Ps[((ty << 2) + i) * AP + (j4 << 2)];
                #pragma unroll
                for (int jj = 0; jj < 4; jj++) {
                    const ulonglong2 vb = *(const ulonglong2*)&Vs[((j4 << 2) + jj) * AP + (tx << 2)];
                    #pragma unroll
                    for (int i = 0; i < 4; i++) {
                        const float* pf = (const float*)&pa[i];
                        const ull pd = dup2(pf[jj]);
                        fma2(acc2[i][0], pd, vb.x);
                        fma2(acc2[i][1], pd, vb.y);
                    }
                }
            }
        }
        #pragma unroll
        for (int i = 0; i < 4; i++) {
            const float inv = 1.f / li[i];
            float2 e0 = unpk(acc2[i][0]), e1 = unpk(acc2[i][1]);
            float4 v = make_float4(e0.x * inv, e0.y * inv, e1.x * inv, e1.y * inv);
            *(float4*)&O[base + (long long)(qt * 64 + (ty << 2) + i) * Cc + (tx << 2)] = v;
        }
    }
}

__global__ void __launch_bounds__(256) ln_k(
    const float* __restrict__ x, const float* __restrict__ g,
    const float* __restrict__ b, float* __restrict__ o)
{
    const int n = blockIdx.x, tid = threadIdx.x;
    const long long rb = (long long)n << 10;
    const int c = tid << 2;
    float4 v = *(const float4*)&x[rb + c];
    float s = v.x + v.y + v.z + v.w;
    float ss = v.x*v.x + v.y*v.y + v.z*v.z + v.w*v.w;
    #pragma unroll
    for (int off = 16; off; off >>= 1) {
        s  += __shfl_xor_sync(0xffffffffu, s, off);
        ss += __shfl_xor_sync(0xffffffffu, ss, off);
    }
    __shared__ float rs[8], rss[8], mv[2];
    const int w = tid >> 5, lane = tid & 31;
    if (!lane) { rs[w] = s; rss[w] = ss; }
    __syncthreads();
    if (tid == 0) {
        float S = 0, SS = 0;
        #pragma unroll
        for (int i = 0; i < 8; i++) { S += rs[i]; SS += rss[i]; }
        const float mean = S * (1.f/1024.f);
        const float var = SS * (1.f/1024.f) - mean * mean;
        mv[0] = mean; mv[1] = rsqrtf(var + 1e-5f);
    }
    __syncthreads();
    const float mean = mv[0], rstd = mv[1];
    float4 gg = *(const float4*)&g[c], bb = *(const float4*)&b[c];
    float4 ov;
    ov.x = (v.x-mean)*rstd*gg.x + bb.x; ov.y = (v.y-mean)*rstd*gg.y + bb.y;
    ov.z = (v.z-mean)*rstd*gg.z + bb.z; ov.w = (v.w-mean)*rstd*gg.w + bb.w;
    *(float4*)&o[rb + c] = ov;
}

__global__ void __launch_bounds__(256) colnorm_k(
    const float* __restrict__ sim, float* __restrict__ colinv)
{
    const int e = blockIdx.x, tid = threadIdx.x;
    float s = 0.f;
    for (int cc = tid; cc < 1024; cc += 256) {
        const float v = sim[cc * 16 + e];
        s = fmaf(v, v, s);
    }
    #pragma unroll
    for (int off = 16; off; off >>= 1) s += __shfl_xor_sync(0xffffffffu, s, off);
    __shared__ float rs[8];
    const int w = tid >> 5, lane = tid & 31;
    if (!lane) rs[w] = s;
    __syncthreads();
    if (tid == 0) {
        float S = 0;
        #pragma unroll
        for (int i = 0; i < 8; i++) S += rs[i];
        colinv[e] = rsqrtf(S);
    }
}

__global__ void __launch_bounds__(256) lnscore_k(
    const float* __restrict__ x1, const float* __restrict__ g, const float* __restrict__ b,
    const float* __restrict__ sim, const float* __restrict__ thr,
    const float* __restrict__ colinv, float* __restrict__ oh2,
    float* __restrict__ oscores, float* __restrict__ okpt, float* __restrict__ maskb,
    int* __restrict__ cnt, int* __restrict__ idxp)
{
    const int n = blockIdx.x, tid = threadIdx.x;
    const long long rb = (long long)n << 10;
    const int c = tid << 2;
    const int w = tid >> 5, lane = tid & 31;

    float4 xv = *(const float4*)&x1[rb + c];
    {
        float s  = xv.x + xv.y + xv.z + xv.w;
        float ss = xv.x*xv.x + xv.y*xv.y + xv.z*xv.z + xv.w*xv.w;
        #pragma unroll
        for (int off = 16; off; off >>= 1) {
            s  += __shfl_xor_sync(0xffffffffu, s, off);
            ss += __shfl_xor_sync(0xffffffffu, ss, off);
        }
        __shared__ float rs0[8], rss0[8], mv[2];
        if (!lane) { rs0[w] = s; rss0[w] = ss; }
        __syncthreads();
        if (tid == 0) {
            float S = 0, SS = 0;
            #pragma unroll
            for (int i = 0; i < 8; i++) { S += rs0[i]; SS += rss0[i]; }
            const float mean = S * (1.f/1024.f);
            const float var = SS * (1.f/1024.f) - mean * mean;
            mv[0] = mean; mv[1] = rsqrtf(var + 1e-5f);
        }
        __syncthreads();
        const float mean = mv[0], rstd = mv[1];
        float4 gg = *(const float4*)&g[c], bb = *(const float4*)&b[c];
        xv.x = (xv.x-mean)*rstd*gg.x + bb.x; xv.y = (xv.y-mean)*rstd*gg.y + bb.y;
        xv.z = (xv.z-mean)*rstd*gg.z + bb.z; xv.w = (xv.w-mean)*rstd*gg.w + bb.w;
        *(float4*)&oh2[rb + c] = xv;
    }
    __syncthreads();

    float ss = xv.x*xv.x + xv.y*xv.y + xv.z*xv.z + xv.w*xv.w;
    float accd[16];
    #pragma unroll
    for (int e = 0; e < 16; e++) accd[e] = 0.f;
    const float hv[4] = {xv.x, xv.y, xv.z, xv.w};
    #pragma unroll
    for (int cc = 0; cc < 4; cc++) {
        const float* sr = &sim[(long long)(c + cc) << 4];
        #pragma unroll
        for (int e = 0; e < 16; e++) accd[e] = fmaf(hv[cc], sr[e], accd[e]);
    }
    #pragma unroll
    for (int off = 16; off; off >>= 1) ss += __shfl_xor_sync(0xffffffffu, ss, off);
    __shared__ float rs[8];
    __shared__ float red[16 * 8];
    __shared__ float smask[16];
    __shared__ float srn;
    if (!lane) rs[w] = ss;
    #pragma unroll
    for (int e = 0; e < 16; e++) {
        float t = accd[e];
        #pragma unroll
        for (int off = 16; off; off >>= 1) t += __shfl_xor_sync(0xffffffffu, t, off);
        if (!lane) red[e * 8 + w] = t;
    }
    __syncthreads();
    if (tid == 0) {
        float S = 0;
        #pragma unroll
        for (int i = 0; i < 8; i++) S += rs[i];
        srn = rsqrtf(S);
    }
    __syncthreads();
    if (tid < 16) {
        float sum = 0;
        #pragma unroll
        for (int i = 0; i < 8; i++) sum += red[tid * 8 + i];
        const float sc = sum * srn * colinv[tid];
        oscores[(n << 4) + tid] = sc;
        const float m = (sc > thr[0]) ? 1.f : 0.f;
        maskb[(n << 4) + tid] = m;
        smask[tid] = m;
        if (m != 0.f) {
            const int pos = atomicAdd(&cnt[tid], 1);
            idxp[tid * Nc + pos] = n;
        }
    }
    __syncthreads();
    if (tid == 0) {
        float kc = 0;
        #pragma unroll
        for (int e = 0; e < 16; e++) kc += smask[e];
        okpt[n] = kc;
    }
}

__global__ void __launch_bounds__(256) final_k(
    const float* __restrict__ x1, const float* __restrict__ eo,
    const float* __restrict__ maskb, float* __restrict__ ox)
{
    const int n = blockIdx.x, tid = threadIdx.x;
    __shared__ float mk[16];
    if (tid < 16) mk[tid] = maskb[(n << 4) + tid];
    __syncthreads();
    const int c = tid << 2;
    const long long rb = (long long)n << 10;
    float4 v = *(const float4*)&x1[rb + c];
    #pragma unroll
    for (int e = 0; e < 16; e++) {
        if (mk[e] != 0.f) {
            const float4 wv = *(const float4*)&eo[(((long long)(n * 16 + e)) << 10) + c];
            v.x += wv.x; v.y += wv.y; v.z += wv.z; v.w += wv.w;
        }
    }
    *(float4*)&ox[rb + c] = v;
}

extern "C" void kernel_launch(void* const* d_in, const int* in_sizes, int n_in,
                              void* d_out, int out_size)
{
    (void)in_sizes; (void)n_in;
    const float* x    = (const float*)d_in[0];
    const float* ln1g = (const float*)d_in[1];
    const float* ln1b = (const float*)d_in[2];
    const float* ln2g = (const float*)d_in[3];
    const float* ln2b = (const float*)d_in[4];
    const float* wq   = (const float*)d_in[5];
    const float* wk   = (const float*)d_in[6];
    const float* wv   = (const float*)d_in[7];
    const float* wo   = (const float*)d_in[8];
    const float* sim  = (const float*)d_in[9];
    const float* thr  = (const float*)d_in[10];
    const float* w1   = (const float*)d_in[11];
    const float* w2   = (const float*)d_in[12];

    float *ph, *pq, *pk, *pv, *pao, *px1, *pmid, *pw1t, *pw2t, *peos, *pmask, *pcol, *pssc, *pkpt;
    int *pcnt, *pidx;
    cudaGetSymbolAddress((void**)&ph, g_h);
    cudaGetSymbolAddress((void**)&pq, g_q);
    cudaGetSymbolAddress((void**)&pk, g_k);
    cudaGetSymbolAddress((void**)&pv, g_v);
    cudaGetSymbolAddress((void**)&pao, g_ao);
    cudaGetSymbolAddress((void**)&px1, g_x1);
    cudaGetSymbolAddress((void**)&pmid, g_mid);
    cudaGetSymbolAddress((void**)&pw1t, g_w1t);
    cudaGetSymbolAddress((void**)&pw2t, g_w2t);
    cudaGetSymbolAddress((void**)&peos, g_eo_scr);
    cudaGetSymbolAddress((void**)&pmask, g_mask);
    cudaGetSymbolAddress((void**)&pcol, g_colinv);
    cudaGetSymbolAddress((void**)&pssc, g_scores_scr);
    cudaGetSymbolAddress((void**)&pkpt, g_kpt_scr);
    cudaGetSymbolAddress((void**)&pcnt, g_cnt);
    cudaGetSymbolAddress((void**)&pidx, g_idx);

    const long long XN  = (long long)Nc * Cc;
    const long long SCN = (long long)Nc * Ec;
    const long long EON = (long long)Nc * Ec * Cc;
    const bool full = ((long long)out_size >= XN + SCN + EON + Nc);
    float* out   = (float*)d_out;
    float* o_x   = out;
    float* o_sc  = full ? out + XN : pssc;
    float* o_eo  = full ? out + XN + SCN : peos;
    float* o_kpt = full ? out + XN + SCN + EON : pkpt;

    cudaFuncSetAttribute(attn2_k, cudaFuncAttributeMaxDynamicSharedMemorySize, SM_ATTN2);
    cudaFuncSetAttribute(moe_g1_k, cudaFuncAttributeMaxDynamicSharedMemorySize, MOE_SMEM);
    cudaFuncSetAttribute(moe_s2_k, cudaFuncAttributeMaxDynamicSharedMemorySize, MOE_SMEM);

    // ---- side stream: independent prep (hidden under main chain) ----
    cudaStream_t s2;
    cudaStreamCreateWithFlags(&s2, cudaStreamNonBlocking);
    cudaEvent_t ev1, evPrep;
    cudaEventCreateWithFlags(&ev1, cudaEventDisableTiming);
    cudaEventCreateWithFlags(&evPrep, cudaEventDisableTiming);
    cudaEventRecord(ev1, 0);
    cudaStreamWaitEvent(s2, ev1, 0);
    zero_eo_k<<<2048, 256, 0, s2>>>((float4*)o_eo, EON / 4);
    zero_cnt_k<<<1, 32, 0, s2>>>(pcnt);
    transpose_k<<<dim3(8, 32, 16), 256, 0, s2>>>(w1, pw1t, Cc, Ic);
    transpose_k<<<dim3(32, 8, 16), 256, 0, s2>>>(w2, pw2t, Ic, Cc);
    colnorm_k<<<16, 256, 0, s2>>>(sim, pcol);
    cudaEventRecord(evPrep, s2);

    // ---- main chain ----
    ln_k<<<Nc, 256>>>(x, ln1g, ln1b, ph);
    gemm_qkv_k<<<dim3(8, 16, 3), 256>>>(ph, wq, wk, wv, pq, pk, pv);
    attn2_k<<<dim3(8, Hc, Bc), 256, SM_ATTN2>>>(pq, pk, pv, pao);
    gemm_res_k<<<dim3(8, 16, 1), 256>>>(pao, wo, px1, x);

    cudaStreamWaitEvent(0, evPrep, 0);
    lnscore_k<<<Nc, 256>>>(px1, ln2g, ln2b, sim, thr, pcol, ph,
                           o_sc, o_kpt, pmask, pcnt, pidx);

    moe_g1_k<<<dim3(2, 16, Ec), 256, MOE_SMEM>>>(ph, pw1t, pmid, pidx, pcnt);
    moe_s2_k<<<dim3(8, 16, Ec), 256, MOE_SMEM>>>(pmid, pw2t, o_eo, pidx, pcnt);

    final_k<<<Nc, 256>>>(px1, o_eo, pmask, o_x);
}

// round 13
// speedup vs baseline: 1.0538x; 1.0229x over previous
#include <cuda_runtime.h>
#include <math.h>
#include <stdint.h>

#define Bc 2
#define Tc 1024
#define Cc 1024
#define Hc 16
#define Dc 64
#define Ec 16
#define Ic 256
#define Nc (Bc*Tc)

typedef unsigned long long ull;

__device__ float g_h  [Nc*Cc];
__device__ float g_q  [Nc*Cc];
__device__ float g_k  [Nc*Cc];
__device__ float g_v  [Nc*Cc];
__device__ float g_ao [Nc*Cc];
__device__ float g_x1 [Nc*Cc];
__device__ float g_mid[(long long)Ec*Nc*Ic];
__device__ float g_w1t[(long long)Ec*Ic*Cc];
__device__ float g_w2t[(long long)Ec*Cc*Ic];
__device__ float g_eo_scr[(long long)Nc*Ec*Cc];
__device__ float g_mask[Nc*Ec];
__device__ float g_colinv[Ec];
__device__ float g_scores_scr[Nc*Ec];
__device__ float g_kpt_scr[Nc];
__device__ int   g_cnt[Ec];
__device__ int   g_idx[Ec*Nc];

__device__ __forceinline__ float gelu_f(float x) {
    return 0.5f * x * (1.0f + erff(x * 0.70710678118654752440f));
}
__device__ __forceinline__ uint32_t smem_u32(const void* p) {
    uint32_t a;
    asm("{ .reg .u64 t; cvta.to.shared.u64 t, %1; cvt.u32.u64 %0, t; }" : "=r"(a) : "l"(p));
    return a;
}
__device__ __forceinline__ float tf32r(float x) {
    float o; asm("cvt.rna.tf32.f32 %0, %1;" : "=f"(o) : "f"(x)); return o;
}
__device__ __forceinline__ void sts128(uint32_t a, float4 v) {
    asm volatile("st.shared.v4.b32 [%0], {%1,%2,%3,%4};" ::
                 "r"(a), "f"(v.x), "f"(v.y), "f"(v.z), "f"(v.w) : "memory");
}
__device__ __forceinline__ void ldsm4(uint32_t (&d)[4], uint32_t addr) {
    asm volatile("ldmatrix.sync.aligned.m8n8.x4.shared.b16 {%0,%1,%2,%3}, [%4];"
                 : "=r"(d[0]), "=r"(d[1]), "=r"(d[2]), "=r"(d[3]) : "r"(addr));
}
__device__ __forceinline__ void mma_tf32(float (&c)[4], const uint32_t (&a)[4], const uint32_t* b) {
    asm volatile("mma.sync.aligned.m16n8k8.row.col.f32.tf32.tf32.f32 "
                 "{%0,%1,%2,%3}, {%4,%5,%6,%7}, {%8,%9}, {%0,%1,%2,%3};"
                 : "+f"(c[0]), "+f"(c[1]), "+f"(c[2]), "+f"(c[3])
                 : "r"(a[0]), "r"(a[1]), "r"(a[2]), "r"(a[3]), "r"(b[0]), "r"(b[1]));
}
__device__ __forceinline__ ull dup2(float x) {
    ull r; asm("mov.b64 %0, {%1,%1};" : "=l"(r) : "f"(x)); return r;
}
__device__ __forceinline__ void fma2(ull &c, ull a, ull b) {
    asm("fma.rn.f32x2 %0, %1, %2, %0;" : "+l"(c) : "l"(a), "l"(b));
}
__device__ __forceinline__ ull mul2(ull a, ull b) {
    ull d; asm("mul.rn.f32x2 %0, %1, %2;" : "=l"(d) : "l"(a), "l"(b)); return d;
}
__device__ __forceinline__ float2 unpk(ull v) {
    float2 f; asm("mov.b64 {%0,%1}, %2;" : "=f"(f.x), "=f"(f.y) : "l"(v)); return f;
}

// ================= MoE tf32 MMA (gathered / scattered) =================
#define MOE_SMEM 65536

__global__ void __launch_bounds__(256) moe_g1_k(
    const float* __restrict__ A, const float* __restrict__ B, float* __restrict__ C,
    const int* __restrict__ idxp, const int* __restrict__ cntp)
{
    extern __shared__ float dsm[];
    const int e = blockIdx.z, tm = blockIdx.y, tn = blockIdx.x;
    const int ce = cntp[e];
    if ((tm << 7) >= ce) return;
    const int tid = threadIdx.x, wid = tid >> 5, lane = tid & 31;
    const int warpM = wid >> 2, warpN = wid & 3;
    const uint32_t sbase = smem_u32(dsm);

    int srcA[4];
    #pragma unroll
    for (int k = 0; k < 4; k++) {
        const int r = (tid + (k << 8)) >> 3;
        int gr = (tm << 7) + r;
        if (gr >= ce) gr = ce - 1;
        srcA[k] = idxp[e * Nc + gr];
    }
    const float* Bt = B + (long long)e * ((long long)Ic * Cc) + ((long long)tn << 7) * Cc;

    float acc[4][4][4];
    #pragma unroll
    for (int i = 0; i < 4; i++)
        #pragma unroll
        for (int j = 0; j < 4; j++)
            #pragma unroll
            for (int r = 0; r < 4; r++) acc[i][j][r] = 0.f;

    auto ldst = [&](int s, int k0) {
        const uint32_t ab = sbase + (uint32_t)s * 32768u;
        const uint32_t bb = ab + 16384u;
        #pragma unroll
        for (int k = 0; k < 4; k++) {
            const int u = tid + (k << 8), r = u >> 3, c = u & 7;
            float4 v = *(const float4*)(A + (long long)srcA[k] * Cc + k0 + (c << 2));
            v = make_float4(tf32r(v.x), tf32r(v.y), tf32r(v.z), tf32r(v.w));
            sts128(ab + ((uint32_t)r << 7) + ((uint32_t)(c ^ (r & 7)) << 4), v);
        }
        #pragma unroll
        for (int k = 0; k < 4; k++) {
            const int u = tid + (k << 8), r = u >> 3, c = u & 7;
            float4 v = *(const float4*)(Bt + (long long)r * Cc + k0 + (c << 2));
            v = make_float4(tf32r(v.x), tf32r(v.y), tf32r(v.z), tf32r(v.w));
            sts128(bb + ((uint32_t)r << 7) + ((uint32_t)(c ^ (r & 7)) << 4), v);
        }
    };

    const int rA = warpM * 64 + ((lane & 8) ? 8 : 0) + (lane & 7);
    const int chA = lane >> 4;
    const int rB = warpN * 32 + ((lane >> 4) << 3) + (lane & 7);
    const int chB = (lane >> 3) & 1;

    ldst(0, 0);
    __syncthreads();
    for (int kc = 0; kc < 32; kc++) {
        if (kc + 1 < 32) ldst((kc + 1) & 1, (kc + 1) << 5);
        const uint32_t ab = sbase + (uint32_t)(kc & 1) * 32768u;
        const uint32_t bb = ab + 16384u;
        #pragma unroll
        for (int k8 = 0; k8 < 4; k8++) {
            uint32_t aF[4][4], bF[2][4];
            #pragma unroll
            for (int mt = 0; mt < 4; mt++) {
                const int rr = rA + mt * 16;
                ldsm4(aF[mt], ab + ((uint32_t)rr << 7) +
                      ((uint32_t)(((k8 << 1) + chA) ^ (rr & 7)) << 4));
            }
            #pragma unroll
            for (int nt2 = 0; nt2 < 2; nt2++) {
                const int rr = rB + nt2 * 16;
                ldsm4(bF[nt2], bb + ((uint32_t)rr << 7) +
                      ((uint32_t)(((k8 << 1) + chB) ^ (rr & 7)) << 4));
            }
            #pragma unroll
            for (int mt = 0; mt < 4; mt++)
                #pragma unroll
                for (int nt = 0; nt < 4; nt++)
                    mma_tf32(acc[mt][nt], aF[mt], &bF[nt >> 1][(nt & 1) << 1]);
        }
        __syncthreads();
    }

    float* Ct = C + (long long)e * ((long long)Nc * Ic);
    const int g = lane >> 2, t4 = lane & 3;
    #pragma unroll
    for (int mt = 0; mt < 4; mt++) {
        const int row0 = (tm << 7) + warpM * 64 + mt * 16 + g;
        #pragma unroll
        for (int nt = 0; nt < 4; nt++) {
            const int col = (tn << 7) + warpN * 32 + nt * 8 + (t4 << 1);
            float2 v0 = make_float2(gelu_f(acc[mt][nt][0]), gelu_f(acc[mt][nt][1]));
            float2 v1 = make_float2(gelu_f(acc[mt][nt][2]), gelu_f(acc[mt][nt][3]));
            *(float2*)&Ct[(long long)row0 * Ic + col] = v0;
            *(float2*)&Ct[(long long)(row0 + 8) * Ic + col] = v1;
        }
    }
}

__global__ void __launch_bounds__(256) moe_s2_k(
    const float* __restrict__ A, const float* __restrict__ B, float* __restrict__ C,
    const int* __restrict__ idxp, const int* __restrict__ cntp)
{
    extern __shared__ float dsm[];
    const int e = blockIdx.z, tm = blockIdx.y, tn = blockIdx.x;
    const int ce = cntp[e];
    if ((tm << 7) >= ce) return;
    const int tid = threadIdx.x, wid = tid >> 5, lane = tid & 31;
    const int warpM = wid >> 2, warpN = wid & 3;
    const uint32_t sbase = smem_u32(dsm);

    const float* At = A + (long long)e * ((long long)Nc * Ic) + ((long long)tm << 7) * Ic;
    const float* Bt = B + (long long)e * ((long long)Cc * Ic) + ((long long)tn << 7) * Ic;

    float acc[4][4][4];
    #pragma unroll
    for (int i = 0; i < 4; i++)
        #pragma unroll
        for (int j = 0; j < 4; j++)
            #pragma unroll
            for (int r = 0; r < 4; r++) acc[i][j][r] = 0.f;

    auto ldst = [&](int s, int k0) {
        const uint32_t ab = sbase + (uint32_t)s * 32768u;
        const uint32_t bb = ab + 16384u;
        #pragma unroll
        for (int k = 0; k < 4; k++) {
            const int u = tid + (k << 8), r = u >> 3, c = u & 7;
            float4 v = *(const float4*)(At + (long long)r * Ic + k0 + (c << 2));
            v = make_float4(tf32r(v.x), tf32r(v.y), tf32r(v.z), tf32r(v.w));
            sts128(ab + ((uint32_t)r << 7) + ((uint32_t)(c ^ (r & 7)) << 4), v);
        }
        #pragma unroll
        for (int k = 0; k < 4; k++) {
            const int u = tid + (k << 8), r = u >> 3, c = u & 7;
            float4 v = *(const float4*)(Bt + (long long)r * Ic + k0 + (c << 2));
            v = make_float4(tf32r(v.x), tf32r(v.y), tf32r(v.z), tf32r(v.w));
            sts128(bb + ((uint32_t)r << 7) + ((uint32_t)(c ^ (r & 7)) << 4), v);
        }
    };

    const int rA = warpM * 64 + ((lane & 8) ? 8 : 0) + (lane & 7);
    const int chA = lane >> 4;
    const int rB = warpN * 32 + ((lane >> 4) << 3) + (lane & 7);
    const int chB = (lane >> 3) & 1;

    ldst(0, 0);
    __syncthreads();
    for (int kc = 0; kc < 8; kc++) {
        if (kc + 1 < 8) ldst((kc + 1) & 1, (kc + 1) << 5);
        const uint32_t ab = sbase + (uint32_t)(kc & 1) * 32768u;
        const uint32_t bb = ab + 16384u;
        #pragma unroll
        for (int k8 = 0; k8 < 4; k8++) {
            uint32_t aF[4][4], bF[2][4];
            #pragma unroll
            for (int mt = 0; mt < 4; mt++) {
                const int rr = rA + mt * 16;
                ldsm4(aF[mt], ab + ((uint32_t)rr << 7) +
                      ((uint32_t)(((k8 << 1) + chA) ^ (rr & 7)) << 4));
            }
            #pragma unroll
            for (int nt2 = 0; nt2 < 2; nt2++) {
                const int rr = rB + nt2 * 16;
                ldsm4(bF[nt2], bb + ((uint32_t)rr << 7) +
                      ((uint32_t)(((k8 << 1) + chB) ^ (rr & 7)) << 4));
            }
            #pragma unroll
            for (int mt = 0; mt < 4; mt++)
                #pragma unroll
                for (int nt = 0; nt < 4; nt++)
                    mma_tf32(acc[mt][nt], aF[mt], &bF[nt >> 1][(nt & 1) << 1]);
        }
        __syncthreads();
    }

    const int g = lane >> 2, t4 = lane & 3;
    #pragma unroll
    for (int mt = 0; mt < 4; mt++) {
        const int rg0 = (tm << 7) + warpM * 64 + mt * 16 + g;
        const int rg1 = rg0 + 8;
        const bool a0 = rg0 < ce, a1 = rg1 < ce;
        const int n0 = a0 ? idxp[e * Nc + rg0] : 0;
        const int n1 = a1 ? idxp[e * Nc + rg1] : 0;
        #pragma unroll
        for (int nt = 0; nt < 4; nt++) {
            const int col = (tn << 7) + warpN * 32 + nt * 8 + (t4 << 1);
            if (a0)
                *(float2*)&C[((long long)n0 * Ec + e) * Cc + col] =
                    make_float2(acc[mt][nt][0], acc[mt][nt][1]);
            if (a1)
                *(float2*)&C[((long long)n1 * Ec + e) * Cc + col] =
                    make_float2(acc[mt][nt][2], acc[mt][nt][3]);
        }
    }
}

__global__ void zero_cnt_k(int* cnt) { if (threadIdx.x < Ec) cnt[threadIdx.x] = 0; }

__global__ void __launch_bounds__(256) zero_eo_k(float4* __restrict__ p, long long n4)
{
    long long i = (long long)blockIdx.x * 256 + threadIdx.x;
    const long long stride = (long long)gridDim.x * 256;
    for (; i < n4; i += stride) p[i] = make_float4(0.f, 0.f, 0.f, 0.f);
}

__global__ void __launch_bounds__(256) transpose_k(
    const float* __restrict__ in, float* __restrict__ out, int R, int C)
{
    __shared__ float t[32][33];
    const long long zo = (long long)blockIdx.z * R * C;
    const int c0 = blockIdx.x << 5, r0 = blockIdx.y << 5;
    const int tx = threadIdx.x & 31, ty = threadIdx.x >> 5;
    #pragma unroll
    for (int k = 0; k < 32; k += 8)
        t[ty + k][tx] = in[zo + (long long)(r0 + ty + k) * C + c0 + tx];
    __syncthreads();
    #pragma unroll
    for (int k = 0; k < 32; k += 8)
        out[zo + (long long)(c0 + ty + k) * R + r0 + tx] = t[tx][ty + k];
}

// ------- fp32 SGEMM, f32x2, BK=16 double-buffered (exact, order-preserving) -------
__device__ __forceinline__ void sgemm_core2(
    const float* __restrict__ A, const float* __restrict__ B,
    int K, int Np, int brow, int bcol, ull acc2[8][4])
{
    __shared__ float As[2][16][128];
    __shared__ float Bs[2][16][128];
    const int tid = threadIdx.x;
    const int ar = tid & 127, ac = (tid >> 7) << 3;
    const int bk = tid >> 4, bcl = (tid & 15) << 3;
    const int tx = tid & 15, ty = tid >> 4;
    const float* Arow = A + (long long)(brow + ar) * K + ac;
    const float* Bbase = B + bcol + bcl + (long long)bk * Np;

    #pragma unroll
    for (int i = 0; i < 8; i++)
        #pragma unroll
        for (int p = 0; p < 4; p++) acc2[i][p] = 0ull;

    float4 la0, la1, lb0, lb1;
    auto ldg = [&](int k0) {
        la0 = *(const float4*)(Arow + k0);
        la1 = *(const float4*)(Arow + k0 + 4);
        lb0 = *(const float4*)(Bbase + (long long)k0 * Np);
        lb1 = *(const float4*)(Bbase + (long long)k0 * Np + 4);
    };
    auto sts = [&](int s) {
        As[s][ac+0][ar] = la0.x; As[s][ac+1][ar] = la0.y;
        As[s][ac+2][ar] = la0.z; As[s][ac+3][ar] = la0.w;
        As[s][ac+4][ar] = la1.x; As[s][ac+5][ar] = la1.y;
        As[s][ac+6][ar] = la1.z; As[s][ac+7][ar] = la1.w;
        *(float4*)&Bs[s][bk][bcl] = lb0;
        *(float4*)&Bs[s][bk][bcl + 4] = lb1;
    };

    const int NC16 = K >> 4;
    ldg(0); sts(0);
    __syncthreads();
    for (int kc = 0; kc < NC16; kc++) {
        if (kc + 1 < NC16) ldg((kc + 1) << 4);
        const int s = kc & 1;
        #pragma unroll
        for (int kk = 0; kk < 16; kk++) {
            float4 a0 = *(const float4*)&As[s][kk][ty << 3];
            float4 a1 = *(const float4*)&As[s][kk][(ty << 3) + 4];
            ulonglong2 b01 = *(const ulonglong2*)&Bs[s][kk][tx << 3];
            ulonglong2 b23 = *(const ulonglong2*)&Bs[s][kk][(tx << 3) + 4];
            ull a2[8];
            a2[0]=dup2(a0.x); a2[1]=dup2(a0.y); a2[2]=dup2(a0.z); a2[3]=dup2(a0.w);
            a2[4]=dup2(a1.x); a2[5]=dup2(a1.y); a2[6]=dup2(a1.z); a2[7]=dup2(a1.w);
            #pragma unroll
            for (int i = 0; i < 8; i++) {
                fma2(acc2[i][0], a2[i], b01.x);
                fma2(acc2[i][1], a2[i], b01.y);
                fma2(acc2[i][2], a2[i], b23.x);
                fma2(acc2[i][3], a2[i], b23.y);
            }
        }
        if (kc + 1 < NC16) sts((kc + 1) & 1);
        __syncthreads();
    }
}

__global__ void __launch_bounds__(256, 2) gemm_res_k(
    const float* __restrict__ A, const float* __restrict__ B, float* __restrict__ C,
    const float* __restrict__ res)
{
    const int brow = blockIdx.y << 7, bcol = blockIdx.x << 7;
    ull acc2[8][4];
    sgemm_core2(A, B, Cc, Cc, brow, bcol, acc2);
    const int tx = threadIdx.x & 15, ty = threadIdx.x >> 4;
    #pragma unroll
    for (int i = 0; i < 8; i++) {
        const int row = brow + (ty << 3) + i;
        #pragma unroll
        for (int p = 0; p < 4; p += 2) {
            const int col = bcol + (tx << 3) + (p << 1);
            float2 e0 = unpk(acc2[i][p]), e1 = unpk(acc2[i][p + 1]);
            float4 v = make_float4(e0.x, e0.y, e1.x, e1.y);
            float4 rv = *(const float4*)&res[(long long)row * Cc + col];
            v.x += rv.x; v.y += rv.y; v.z += rv.z; v.w += rv.w;
            *(float4*)&C[(long long)row * Cc + col] = v;
        }
    }
}

__global__ void __launch_bounds__(256, 2) gemm_qkv_k(
    const float* __restrict__ A,
    const float* __restrict__ b0, const float* __restrict__ b1, const float* __restrict__ b2,
    float* __restrict__ c0, float* __restrict__ c1, float* __restrict__ c2)
{
    const int z = blockIdx.z;
    const float* B = (z == 0) ? b0 : (z == 1) ? b1 : b2;
    float* C = (z == 0) ? c0 : (z == 1) ? c1 : c2;
    const int brow = blockIdx.y << 7, bcol = blockIdx.x << 7;
    ull acc2[8][4];
    sgemm_core2(A, B, Cc, Cc, brow, bcol, acc2);
    const int tx = threadIdx.x & 15, ty = threadIdx.x >> 4;
    #pragma unroll
    for (int i = 0; i < 8; i++) {
        const int row = brow + (ty << 3) + i;
        #pragma unroll
        for (int p = 0; p < 4; p += 2) {
            const int col = bcol + (tx << 3) + (p << 1);
            float2 e0 = unpk(acc2[i][p]), e1 = unpk(acc2[i][p + 1]);
            *(float4*)&C[(long long)row * Cc + col] = make_float4(e0.x, e0.y, e1.x, e1.y);
        }
    }
}

// ------- flash attention: 288 near-uniform blocks, exp2 phase softmax -------
#define AP 68
#define SM_ATTN2 (4 * 64 * AP * 4)
#define QSCALE 0.18033688011112042592f   /* 0.125 * log2(e) */
__global__ void __launch_bounds__(256) attn2_k(
    const float* __restrict__ Q, const float* __restrict__ K,
    const float* __restrict__ V, float* __restrict__ O)
{
    extern __shared__ float sm[];
    float* Qs = sm;
    float* Ks = sm + 64 * AP;
    float* Vs = sm + 2 * 64 * AP;
    float* Ps = sm + 3 * 64 * AP;
    const int bid = blockIdx.x;
    // schedule: bid<64 -> single {qt15 (bid<32) or qt14}; else pairs (pi, 13-pi)
    int combo, nseg, q0, q1;
    if (bid < 64) {
        combo = bid & 31; nseg = 1;
        q0 = 15 - (bid >> 5); q1 = 0;
    } else {
        const int pid = bid - 64;
        combo = pid & 31; nseg = 2;
        const int pi = pid >> 5;
        q0 = 13 - pi; q1 = pi;     // bigger segment first
    }
    const int h = combo & 15, b = combo >> 4;
    const int tid = threadIdx.x;
    const int tx = tid & 15, ty = tid >> 4;
    const long long base = ((long long)b * Tc) * Cc + h * Dc;
    const int lr = tid >> 4;
    const int lc = (tid & 15) << 2;

    for (int seg = 0; seg < nseg; seg++) {
        const int qt = seg ? q1 : q0;
        __syncthreads();
        #pragma unroll
        for (int rep = 0; rep < 4; rep++) {
            const int r = lr + (rep << 4);
            float4 v = *(const float4*)&Q[base + (long long)(qt * 64 + r) * Cc + lc];
            v.x *= QSCALE; v.y *= QSCALE; v.z *= QSCALE; v.w *= QSCALE;
            *(float4*)&Qs[r * AP + lc] = v;
        }

        ull acc2[4][2];
        float mi[4], li[4];
        #pragma unroll
        for (int i = 0; i < 4; i++) { acc2[i][0] = 0ull; acc2[i][1] = 0ull; mi[i] = -1e30f; li[i] = 0.f; }

        float4 kr[4], vr[4];
        #pragma unroll
        for (int rep = 0; rep < 4; rep++) {
            const int r = lr + (rep << 4);
            kr[rep] = *(const float4*)&K[base + (long long)r * Cc + lc];
            vr[rep] = *(const float4*)&V[base + (long long)r * Cc + lc];
        }

        for (int kt = 0; kt <= qt; kt++) {
            __syncthreads();
            #pragma unroll
            for (int rep = 0; rep < 4; rep++) {
                const int r = lr + (rep << 4);
                *(float4*)&Ks[r * AP + lc] = kr[rep];
                *(float4*)&Vs[r * AP + lc] = vr[rep];
            }
            __syncthreads();
            if (kt < qt) {
                #pragma unroll
                for (int rep = 0; rep < 4; rep++) {
                    const int r = lr + (rep << 4);
                    kr[rep] = *(const float4*)&K[base + (long long)((kt + 1) * 64 + r) * Cc + lc];
                    vr[rep] = *(const float4*)&V[base + (long long)((kt + 1) * 64 + r) * Cc + lc];
                }
            }
            ull s2[4][4];
            #pragma unroll
            for (int i = 0; i < 4; i++)
                #pragma unroll
                for (int j = 0; j < 4; j++) s2[i][j] = 0ull;
            #pragma unroll 4
            for (int d4 = 0; d4 < 16; d4++) {
                ulonglong2 la[4], lb[4];
                #pragma unroll
                for (int i = 0; i < 4; i++)
                    la[i] = *(const ulonglong2*)&Qs[((ty << 2) + i) * AP + (d4 << 2)];
                #pragma unroll
                for (int j = 0; j < 4; j++)
                    lb[j] = *(const ulonglong2*)&Ks[(tx + (j << 4)) * AP + (d4 << 2)];
                #pragma unroll
                for (int i = 0; i < 4; i++)
                    #pragma unroll
                    for (int j = 0; j < 4; j++) {
                        fma2(s2[i][j], la[i].x, lb[j].x);
                        fma2(s2[i][j], la[i].y, lb[j].y);
                    }
            }
            const bool diag = (kt == qt);
            float p[4][4], mloc[4];
            #pragma unroll
            for (int i = 0; i < 4; i++) {
                mloc[i] = -1e30f;
                #pragma unroll
                for (int j = 0; j < 4; j++) {
                    float2 u = unpk(s2[i][j]);
                    float sv = u.x + u.y;
                    if (diag && (tx + (j << 4)) > ((ty << 2) + i)) sv = -1e30f;
                    p[i][j] = sv;
                    mloc[i] = fmaxf(mloc[i], sv);
                }
            }
            #pragma unroll
            for (int st = 1; st <= 8; st <<= 1)
                #pragma unroll
                for (int i = 0; i < 4; i++)
                    mloc[i] = fmaxf(mloc[i], __shfl_xor_sync(0xffffffffu, mloc[i], st));
            float alpha[4], ps[4];
            #pragma unroll
            for (int i = 0; i < 4; i++) {
                const float mnew = fmaxf(mi[i], mloc[i]);
                alpha[i] = exp2f(mi[i] - mnew);
                mi[i] = mnew;
                ps[i] = 0.f;
                #pragma unroll
                for (int j = 0; j < 4; j++) {
                    p[i][j] = exp2f(p[i][j] - mnew);
                    ps[i] += p[i][j];
                }
            }
            #pragma unroll
            for (int st = 1; st <= 8; st <<= 1)
                #pragma unroll
                for (int i = 0; i < 4; i++)
                    ps[i] += __shfl_xor_sync(0xffffffffu, ps[i], st);
            #pragma unroll
            for (int i = 0; i < 4; i++) {
                li[i] = li[i] * alpha[i] + ps[i];
                const ull ad = dup2(alpha[i]);
                acc2[i][0] = mul2(acc2[i][0], ad);
                acc2[i][1] = mul2(acc2[i][1], ad);
                float* pr = &Ps[((ty << 2) + i) * AP + tx];
                pr[0] = p[i][0]; pr[16] = p[i][1]; pr[32] = p[i][2]; pr[48] = p[i][3];
            }
            __syncthreads();
            #pragma unroll 4
            for (int j4 = 0; j4 < 16; j4++) {
                float4 pa[4];
                #pragma unroll
                for (int i = 0; i < 4; i++)
                    pa[i] = *(const float4*)&Ps[((ty << 2) + i) * AP + (j4 << 2)];
                #pragma unroll
                for (int jj = 0; jj < 4; jj++) {
                    const ulonglong2 vb = *(const ulonglong2*)&Vs[((j4 << 2) + jj) * AP + (tx << 2)];
                    #pragma unroll
                    for (int i = 0; i < 4; i++) {
                        const float* pf = (const float*)&pa[i];
                        const ull pd = dup2(pf[jj]);
                        fma2(acc2[i][0], pd, vb.x);
                        fma2(acc2[i][1], pd, vb.y);
                    }
                }
            }
        }
        #pragma unroll
        for (int i = 0; i < 4; i++) {
            const float inv = 1.f / li[i];
            float2 e0 = unpk(acc2[i][0]), e1 = unpk(acc2[i][1]);
            float4 v = make_float4(e0.x * inv, e0.y * inv, e1.x * inv, e1.y * inv);
            *(float4*)&O[base + (long long)(qt * 64 + (ty << 2) + i) * Cc + (tx << 2)] = v;
        }
    }
}

__global__ void __launch_bounds__(256) ln_k(
    const float* __restrict__ x, const float* __restrict__ g,
    const float* __restrict__ b, float* __restrict__ o)
{
    const int n = blockIdx.x, tid = threadIdx.x;
    const long long rb = (long long)n << 10;
    const int c = tid << 2;
    float4 v = *(const float4*)&x[rb + c];
    float s = v.x + v.y + v.z + v.w;
    float ss = v.x*v.x + v.y*v.y + v.z*v.z + v.w*v.w;
    #pragma unroll
    for (int off = 16; off; off >>= 1) {
        s  += __shfl_xor_sync(0xffffffffu, s, off);
        ss += __shfl_xor_sync(0xffffffffu, ss, off);
    }
    __shared__ float rs[8], rss[8], mv[2];
    const int w = tid >> 5, lane = tid & 31;
    if (!lane) { rs[w] = s; rss[w] = ss; }
    __syncthreads();
    if (tid == 0) {
        float S = 0, SS = 0;
        #pragma unroll
        for (int i = 0; i < 8; i++) { S += rs[i]; SS += rss[i]; }
        const float mean = S * (1.f/1024.f);
        const float var = SS * (1.f/1024.f) - mean * mean;
        mv[0] = mean; mv[1] = rsqrtf(var + 1e-5f);
    }
    __syncthreads();
    const float mean = mv[0], rstd = mv[1];
    float4 gg = *(const float4*)&g[c], bb = *(const float4*)&b[c];
    float4 ov;
    ov.x = (v.x-mean)*rstd*gg.x + bb.x; ov.y = (v.y-mean)*rstd*gg.y + bb.y;
    ov.z = (v.z-mean)*rstd*gg.z + bb.z; ov.w = (v.w-mean)*rstd*gg.w + bb.w;
    *(float4*)&o[rb + c] = ov;
}

__global__ void __launch_bounds__(256) colnorm_k(
    const float* __restrict__ sim, float* __restrict__ colinv)
{
    const int e = blockIdx.x, tid = threadIdx.x;
    float s = 0.f;
    for (int cc = tid; cc < 1024; cc += 256) {
        const float v = sim[cc * 16 + e];
        s = fmaf(v, v, s);
    }
    #pragma unroll
    for (int off = 16; off; off >>= 1) s += __shfl_xor_sync(0xffffffffu, s, off);
    __shared__ float rs[8];
    const int w = tid >> 5, lane = tid & 31;
    if (!lane) rs[w] = s;
    __syncthreads();
    if (tid == 0) {
        float S = 0;
        #pragma unroll
        for (int i = 0; i < 8; i++) S += rs[i];
        colinv[e] = rsqrtf(S);
    }
}

__global__ void __launch_bounds__(256) lnscore_k(
    const float* __restrict__ x1, const float* __restrict__ g, const float* __restrict__ b,
    const float* __restrict__ sim, const float* __restrict__ thr,
    const float* __restrict__ colinv, float* __restrict__ oh2,
    float* __restrict__ oscores, float* __restrict__ okpt, float* __restrict__ maskb,
    int* __restrict__ cnt, int* __restrict__ idxp)
{
    const int n = blockIdx.x, tid = threadIdx.x;
    const long long rb = (long long)n << 10;
    const int c = tid << 2;
    const int w = tid >> 5, lane = tid & 31;

    float4 xv = *(const float4*)&x1[rb + c];
    {
        float s  = xv.x + xv.y + xv.z + xv.w;
        float ss = xv.x*xv.x + xv.y*xv.y + xv.z*xv.z + xv.w*xv.w;
        #pragma unroll
        for (int off = 16; off; off >>= 1) {
            s  += __shfl_xor_sync(0xffffffffu, s, off);
            ss += __shfl_xor_sync(0xffffffffu, ss, off);
        }
        __shared__ float rs0[8], rss0[8], mv[2];
        if (!lane) { rs0[w] = s; rss0[w] = ss; }
        __syncthreads();
        if (tid == 0) {
            float S = 0, SS = 0;
            #pragma unroll
            for (int i = 0; i < 8; i++) { S += rs0[i]; SS += rss0[i]; }
            const float mean = S * (1.f/1024.f);
            const float var = SS * (1.f/1024.f) - mean * mean;
            mv[0] = mean; mv[1] = rsqrtf(var + 1e-5f);
        }
        __syncthreads();
        const float mean = mv[0], rstd = mv[1];
        float4 gg = *(const float4*)&g[c], bb = *(const float4*)&b[c];
        xv.x = (xv.x-mean)*rstd*gg.x + bb.x; xv.y = (xv.y-mean)*rstd*gg.y + bb.y;
        xv.z = (xv.z-mean)*rstd*gg.z + bb.z; xv.w = (xv.w-mean)*rstd*gg.w + bb.w;
        *(float4*)&oh2[rb + c] = xv;
    }
    __syncthreads();

    float ss = xv.x*xv.x + xv.y*xv.y + xv.z*xv.z + xv.w*xv.w;
    float accd[16];
    #pragma unroll
    for (int e = 0; e < 16; e++) accd[e] = 0.f;
    const float hv[4] = {xv.x, xv.y, xv.z, xv.w};
    #pragma unroll
    for (int cc = 0; cc < 4; cc++) {
        const float* sr = &sim[(long long)(c + cc) << 4];
        #pragma unroll
        for (int e = 0; e < 16; e++) accd[e] = fmaf(hv[cc], sr[e], accd[e]);
    }
    #pragma unroll
    for (int off = 16; off; off >>= 1) ss += __shfl_xor_sync(0xffffffffu, ss, off);
    __shared__ float rs[8];
    __shared__ float red[16 * 8];
    __shared__ float smask[16];
    __shared__ float srn;
    if (!lane) rs[w] = ss;
    #pragma unroll
    for (int e = 0; e < 16; e++) {
        float t = accd[e];
        #pragma unroll
        for (int off = 16; off; off >>= 1) t += __shfl_xor_sync(0xffffffffu, t, off);
        if (!lane) red[e * 8 + w] = t;
    }
    __syncthreads();
    if (tid == 0) {
        float S = 0;
        #pragma unroll
        for (int i = 0; i < 8; i++) S += rs[i];
        srn = rsqrtf(S);
    }
    __syncthreads();
    if (tid < 16) {
        float sum = 0;
        #pragma unroll
        for (int i = 0; i < 8; i++) sum += red[tid * 8 + i];
        const float sc = sum * srn * colinv[tid];
        oscores[(n << 4) + tid] = sc;
        const float m = (sc > thr[0]) ? 1.f : 0.f;
        maskb[(n << 4) + tid] = m;
        smask[tid] = m;
        if (m != 0.f) {
            const int pos = atomicAdd(&cnt[tid], 1);
            idxp[tid * Nc + pos] = n;
        }
    }
    __syncthreads();
    if (tid == 0) {
        float kc = 0;
        #pragma unroll
        for (int e = 0; e < 16; e++) kc += smask[e];
        okpt[n] = kc;
    }
}

__global__ void __launch_bounds__(256) final_k(
    const float* __restrict__ x1, const float* __restrict__ eo,
    const float* __restrict__ maskb, float* __restrict__ ox)
{
    const int n = blockIdx.x, tid = threadIdx.x;
    __shared__ float mk[16];
    if (tid < 16) mk[tid] = maskb[(n << 4) + tid];
    __syncthreads();
    const int c = tid << 2;
    const long long rb = (long long)n << 10;
    float4 v = *(const float4*)&x1[rb + c];
    #pragma unroll
    for (int e = 0; e < 16; e++) {
        if (mk[e] != 0.f) {
            const float4 wv = *(const float4*)&eo[(((long long)(n * 16 + e)) << 10) + c];
            v.x += wv.x; v.y += wv.y; v.z += wv.z; v.w += wv.w;
        }
    }
    *(float4*)&ox[rb + c] = v;
}

extern "C" void kernel_launch(void* const* d_in, const int* in_sizes, int n_in,
                              void* d_out, int out_size)
{
    (void)in_sizes; (void)n_in;
    const float* x    = (const float*)d_in[0];
    const float* ln1g = (const float*)d_in[1];
    const float* ln1b = (const float*)d_in[2];
    const float* ln2g = (const float*)d_in[3];
    const float* ln2b = (const float*)d_in[4];
    const float* wq   = (const float*)d_in[5];
    const float* wk   = (const float*)d_in[6];
    const float* wv   = (const float*)d_in[7];
    const float* wo   = (const float*)d_in[8];
    const float* sim  = (const float*)d_in[9];
    const float* thr  = (const float*)d_in[10];
    const float* w1   = (const float*)d_in[11];
    const float* w2   = (const float*)d_in[12];

    float *ph, *pq, *pk, *pv, *pao, *px1, *pmid, *pw1t, *pw2t, *peos, *pmask, *pcol, *pssc, *pkpt;
    int *pcnt, *pidx;
    cudaGetSymbolAddress((void**)&ph, g_h);
    cudaGetSymbolAddress((void**)&pq, g_q);
    cudaGetSymbolAddress((void**)&pk, g_k);
    cudaGetSymbolAddress((void**)&pv, g_v);
    cudaGetSymbolAddress((void**)&pao, g_ao);
    cudaGetSymbolAddress((void**)&px1, g_x1);
    cudaGetSymbolAddress((void**)&pmid, g_mid);
    cudaGetSymbolAddress((void**)&pw1t, g_w1t);
    cudaGetSymbolAddress((void**)&pw2t, g_w2t);
    cudaGetSymbolAddress((void**)&peos, g_eo_scr);
    cudaGetSymbolAddress((void**)&pmask, g_mask);
    cudaGetSymbolAddress((void**)&pcol, g_colinv);
    cudaGetSymbolAddress((void**)&pssc, g_scores_scr);
    cudaGetSymbolAddress((void**)&pkpt, g_kpt_scr);
    cudaGetSymbolAddress((void**)&pcnt, g_cnt);
    cudaGetSymbolAddress((void**)&pidx, g_idx);

    const long long XN  = (long long)Nc * Cc;
    const long long SCN = (long long)Nc * Ec;
    const long long EON = (long long)Nc * Ec * Cc;
    const bool full = ((long long)out_size >= XN + SCN + EON + Nc);
    float* out   = (float*)d_out;
    float* o_x   = out;
    float* o_sc  = full ? out + XN : pssc;
    float* o_eo  = full ? out + XN + SCN : peos;
    float* o_kpt = full ? out + XN + SCN + EON : pkpt;

    cudaFuncSetAttribute(attn2_k, cudaFuncAttributeMaxDynamicSharedMemorySize, SM_ATTN2);
    cudaFuncSetAttribute(moe_g1_k, cudaFuncAttributeMaxDynamicSharedMemorySize, MOE_SMEM);
    cudaFuncSetAttribute(moe_s2_k, cudaFuncAttributeMaxDynamicSharedMemorySize, MOE_SMEM);

    // ---- side stream: independent prep (hidden under main chain) ----
    cudaStream_t s2;
    cudaStreamCreateWithFlags(&s2, cudaStreamNonBlocking);
    cudaEvent_t ev1, evPrep;
    cudaEventCreateWithFlags(&ev1, cudaEventDisableTiming);
    cudaEventCreateWithFlags(&evPrep, cudaEventDisableTiming);
    cudaEventRecord(ev1, 0);
    cudaStreamWaitEvent(s2, ev1, 0);
    zero_eo_k<<<2048, 256, 0, s2>>>((float4*)o_eo, EON / 4);
    zero_cnt_k<<<1, 32, 0, s2>>>(pcnt);
    transpose_k<<<dim3(8, 32, 16), 256, 0, s2>>>(w1, pw1t, Cc, Ic);
    transpose_k<<<dim3(32, 8, 16), 256, 0, s2>>>(w2, pw2t, Ic, Cc);
    colnorm_k<<<16, 256, 0, s2>>>(sim, pcol);
    cudaEventRecord(evPrep, s2);

    // ---- main chain ----
    ln_k<<<Nc, 256>>>(x, ln1g, ln1b, ph);
    gemm_qkv_k<<<dim3(8, 16, 3), 256>>>(ph, wq, wk, wv, pq, pk, pv);
    attn2_k<<<288, 256, SM_ATTN2>>>(pq, pk, pv, pao);
    gemm_res_k<<<dim3(8, 16, 1), 256>>>(pao, wo, px1, x);

    cudaStreamWaitEvent(0, evPrep, 0);
    lnscore_k<<<Nc, 256>>>(px1, ln2g, ln2b, sim, thr, pcol, ph,
                           o_sc, o_kpt, pmask, pcnt, pidx);

    moe_g1_k<<<dim3(2, 16, Ec), 256, MOE_SMEM>>>(ph, pw1t, pmid, pidx, pcnt);
    moe_s2_k<<<dim3(8, 16, Ec), 256, MOE_SMEM>>>(pmid, pw2t, o_eo, pidx, pcnt);

    final_k<<<Nc, 256>>>(px1, o_eo, pmask, o_x);
}

// round 15
// speedup vs baseline: 1.0565x; 1.0026x over previous
#include <cuda_runtime.h>
#include <math.h>
#include <stdint.h>

#define Bc 2
#define Tc 1024
#define Cc 1024
#define Hc 16
#define Dc 64
#define Ec 16
#define Ic 256
#define Nc (Bc*Tc)

typedef unsigned long long ull;

__device__ float g_h  [Nc*Cc];
__device__ float g_q  [Nc*Cc];
__device__ float g_k  [Nc*Cc];
__device__ float g_v  [Nc*Cc];
__device__ float g_ao [Nc*Cc];
__device__ float g_x1 [Nc*Cc];
__device__ float g_mid[(long long)Ec*Nc*Ic];
__device__ float g_w1t[(long long)Ec*Ic*Cc];
__device__ float g_w2t[(long long)Ec*Cc*Ic];
__device__ float g_eo_scr[(long long)Nc*Ec*Cc];
__device__ float g_mask[Nc*Ec];
__device__ float g_colinv[Ec];
__device__ float g_scores_scr[Nc*Ec];
__device__ float g_kpt_scr[Nc];
__device__ int   g_cnt[Ec];
__device__ int   g_idx[Ec*Nc];
__device__ int   g_qkv_ctr;

__device__ __forceinline__ float gelu_f(float x) {
    return 0.5f * x * (1.0f + erff(x * 0.70710678118654752440f));
}
__device__ __forceinline__ uint32_t smem_u32(const void* p) {
    uint32_t a;
    asm("{ .reg .u64 t; cvta.to.shared.u64 t, %1; cvt.u32.u64 %0, t; }" : "=r"(a) : "l"(p));
    return a;
}
__device__ __forceinline__ float tf32r(float x) {
    float o; asm("cvt.rna.tf32.f32 %0, %1;" : "=f"(o) : "f"(x)); return o;
}
__device__ __forceinline__ void sts128(uint32_t a, float4 v) {
    asm volatile("st.shared.v4.b32 [%0], {%1,%2,%3,%4};" ::
                 "r"(a), "f"(v.x), "f"(v.y), "f"(v.z), "f"(v.w) : "memory");
}
__device__ __forceinline__ void ldsm4(uint32_t (&d)[4], uint32_t addr) {
    asm volatile("ldmatrix.sync.aligned.m8n8.x4.shared.b16 {%0,%1,%2,%3}, [%4];"
                 : "=r"(d[0]), "=r"(d[1]), "=r"(d[2]), "=r"(d[3]) : "r"(addr));
}
__device__ __forceinline__ void mma_tf32(float (&c)[4], const uint32_t (&a)[4], const uint32_t* b) {
    asm volatile("mma.sync.aligned.m16n8k8.row.col.f32.tf32.tf32.f32 "
                 "{%0,%1,%2,%3}, {%4,%5,%6,%7}, {%8,%9}, {%0,%1,%2,%3};"
                 : "+f"(c[0]), "+f"(c[1]), "+f"(c[2]), "+f"(c[3])
                 : "r"(a[0]), "r"(a[1]), "r"(a[2]), "r"(a[3]), "r"(b[0]), "r"(b[1]));
}
__device__ __forceinline__ ull dup2(float x) {
    ull r; asm("mov.b64 %0, {%1,%1};" : "=l"(r) : "f"(x)); return r;
}
__device__ __forceinline__ void fma2(ull &c, ull a, ull b) {
    asm("fma.rn.f32x2 %0, %1, %2, %0;" : "+l"(c) : "l"(a), "l"(b));
}
__device__ __forceinline__ ull mul2(ull a, ull b) {
    ull d; asm("mul.rn.f32x2 %0, %1, %2;" : "=l"(d) : "l"(a), "l"(b)); return d;
}
__device__ __forceinline__ float2 unpk(ull v) {
    float2 f; asm("mov.b64 {%0,%1}, %2;" : "=f"(f.x), "=f"(f.y) : "l"(v)); return f;
}

// ================= MoE tf32 MMA (gathered / scattered) =================
#define MOE_SMEM 65536

__global__ void __launch_bounds__(256) moe_g1_k(
    const float* __restrict__ A, const float* __restrict__ B, float* __restrict__ C,
    const int* __restrict__ idxp, const int* __restrict__ cntp)
{
    extern __shared__ float dsm[];
    const int e = blockIdx.z, tm = blockIdx.y, tn = blockIdx.x;
    const int ce = cntp[e];
    if ((tm << 7) >= ce) return;
    const int tid = threadIdx.x, wid = tid >> 5, lane = tid & 31;
    const int warpM = wid >> 2, warpN = wid & 3;
    const uint32_t sbase = smem_u32(dsm);

    int srcA[4];
    #pragma unroll
    for (int k = 0; k < 4; k++) {
        const int r = (tid + (k << 8)) >> 3;
        int gr = (tm << 7) + r;
        if (gr >= ce) gr = ce - 1;
        srcA[k] = idxp[e * Nc + gr];
    }
    const float* Bt = B + (long long)e * ((long long)Ic * Cc) + ((long long)tn << 7) * Cc;

    float acc[4][4][4];
    #pragma unroll
    for (int i = 0; i < 4; i++)
        #pragma unroll
        for (int j = 0; j < 4; j++)
            #pragma unroll
            for (int r = 0; r < 4; r++) acc[i][j][r] = 0.f;

    auto ldst = [&](int s, int k0) {
        const uint32_t ab = sbase + (uint32_t)s * 32768u;
        const uint32_t bb = ab + 16384u;
        #pragma unroll
        for (int k = 0; k < 4; k++) {
            const int u = tid + (k << 8), r = u >> 3, c = u & 7;
            float4 v = *(const float4*)(A + (long long)srcA[k] * Cc + k0 + (c << 2));
            v = make_float4(tf32r(v.x), tf32r(v.y), tf32r(v.z), tf32r(v.w));
            sts128(ab + ((uint32_t)r << 7) + ((uint32_t)(c ^ (r & 7)) << 4), v);
        }
        #pragma unroll
        for (int k = 0; k < 4; k++) {
            const int u = tid + (k << 8), r = u >> 3, c = u & 7;
            float4 v = *(const float4*)(Bt + (long long)r * Cc + k0 + (c << 2));
            v = make_float4(tf32r(v.x), tf32r(v.y), tf32r(v.z), tf32r(v.w));
            sts128(bb + ((uint32_t)r << 7) + ((uint32_t)(c ^ (r & 7)) << 4), v);
        }
    };

    const int rA = warpM * 64 + ((lane & 8) ? 8 : 0) + (lane & 7);
    const int chA = lane >> 4;
    const int rB = warpN * 32 + ((lane >> 4) << 3) + (lane & 7);
    const int chB = (lane >> 3) & 1;

    ldst(0, 0);
    __syncthreads();
    for (int kc = 0; kc < 32; kc++) {
        if (kc + 1 < 32) ldst((kc + 1) & 1, (kc + 1) << 5);
        const uint32_t ab = sbase + (uint32_t)(kc & 1) * 32768u;
        const uint32_t bb = ab + 16384u;
        #pragma unroll
        for (int k8 = 0; k8 < 4; k8++) {
            uint32_t aF[4][4], bF[2][4];
            #pragma unroll
            for (int mt = 0; mt < 4; mt++) {
                const int rr = rA + mt * 16;
                ldsm4(aF[mt], ab + ((uint32_t)rr << 7) +
                      ((uint32_t)(((k8 << 1) + chA) ^ (rr & 7)) << 4));
            }
            #pragma unroll
            for (int nt2 = 0; nt2 < 2; nt2++) {
                const int rr = rB + nt2 * 16;
                ldsm4(bF[nt2], bb + ((uint32_t)rr << 7) +
                      ((uint32_t)(((k8 << 1) + chB) ^ (rr & 7)) << 4));
            }
            #pragma unroll
            for (int mt = 0; mt < 4; mt++)
                #pragma unroll
                for (int nt = 0; nt < 4; nt++)
                    mma_tf32(acc[mt][nt], aF[mt], &bF[nt >> 1][(nt & 1) << 1]);
        }
        __syncthreads();
    }

    float* Ct = C + (long long)e * ((long long)Nc * Ic);
    const int g = lane >> 2, t4 = lane & 3;
    #pragma unroll
    for (int mt = 0; mt < 4; mt++) {
        const int row0 = (tm << 7) + warpM * 64 + mt * 16 + g;
        #pragma unroll
        for (int nt = 0; nt < 4; nt++) {
            const int col = (tn << 7) + warpN * 32 + nt * 8 + (t4 << 1);
            float2 v0 = make_float2(gelu_f(acc[mt][nt][0]), gelu_f(acc[mt][nt][1]));
            float2 v1 = make_float2(gelu_f(acc[mt][nt][2]), gelu_f(acc[mt][nt][3]));
            *(float2*)&Ct[(long long)row0 * Ic + col] = v0;
            *(float2*)&Ct[(long long)(row0 + 8) * Ic + col] = v1;
        }
    }
}

__global__ void __launch_bounds__(256) moe_s2_k(
    const float* __restrict__ A, const float* __restrict__ B, float* __restrict__ C,
    const int* __restrict__ idxp, const int* __restrict__ cntp)
{
    extern __shared__ float dsm[];
    const int e = blockIdx.z, tm = blockIdx.y, tn = blockIdx.x;
    const int ce = cntp[e];
    if ((tm << 7) >= ce) return;
    const int tid = threadIdx.x, wid = tid >> 5, lane = tid & 31;
    const int warpM = wid >> 2, warpN = wid & 3;
    const uint32_t sbase = smem_u32(dsm);

    const float* At = A + (long long)e * ((long long)Nc * Ic) + ((long long)tm << 7) * Ic;
    const float* Bt = B + (long long)e * ((long long)Cc * Ic) + ((long long)tn << 7) * Ic;

    float acc[4][4][4];
    #pragma unroll
    for (int i = 0; i < 4; i++)
        #pragma unroll
        for (int j = 0; j < 4; j++)
            #pragma unroll
            for (int r = 0; r < 4; r++) acc[i][j][r] = 0.f;

    auto ldst = [&](int s, int k0) {
        const uint32_t ab = sbase + (uint32_t)s * 32768u;
        const uint32_t bb = ab + 16384u;
        #pragma unroll
        for (int k = 0; k < 4; k++) {
            const int u = tid + (k << 8), r = u >> 3, c = u & 7;
            float4 v = *(const float4*)(At + (long long)r * Ic + k0 + (c << 2));
            v = make_float4(tf32r(v.x), tf32r(v.y), tf32r(v.z), tf32r(v.w));
            sts128(ab + ((uint32_t)r << 7) + ((uint32_t)(c ^ (r & 7)) << 4), v);
        }
        #pragma unroll
        for (int k = 0; k < 4; k++) {
            const int u = tid + (k << 8), r = u >> 3, c = u & 7;
            float4 v = *(const float4*)(Bt + (long long)r * Ic + k0 + (c << 2));
            v = make_float4(tf32r(v.x), tf32r(v.y), tf32r(v.z), tf32r(v.w));
            sts128(bb + ((uint32_t)r << 7) + ((uint32_t)(c ^ (r & 7)) << 4), v);
        }
    };

    const int rA = warpM * 64 + ((lane & 8) ? 8 : 0) + (lane & 7);
    const int chA = lane >> 4;
    const int rB = warpN * 32 + ((lane >> 4) << 3) + (lane & 7);
    const int chB = (lane >> 3) & 1;

    ldst(0, 0);
    __syncthreads();
    for (int kc = 0; kc < 8; kc++) {
        if (kc + 1 < 8) ldst((kc + 1) & 1, (kc + 1) << 5);
        const uint32_t ab = sbase + (uint32_t)(kc & 1) * 32768u;
        const uint32_t bb = ab + 16384u;
        #pragma unroll
        for (int k8 = 0; k8 < 4; k8++) {
            uint32_t aF[4][4], bF[2][4];
            #pragma unroll
            for (int mt = 0; mt < 4; mt++) {
                const int rr = rA + mt * 16;
                ldsm4(aF[mt], ab + ((uint32_t)rr << 7) +
                      ((uint32_t)(((k8 << 1) + chA) ^ (rr & 7)) << 4));
            }
            #pragma unroll
            for (int nt2 = 0; nt2 < 2; nt2++) {
                const int rr = rB + nt2 * 16;
                ldsm4(bF[nt2], bb + ((uint32_t)rr << 7) +
                      ((uint32_t)(((k8 << 1) + chB) ^ (rr & 7)) << 4));
            }
            #pragma unroll
            for (int mt = 0; mt < 4; mt++)
                #pragma unroll
                for (int nt = 0; nt < 4; nt++)
                    mma_tf32(acc[mt][nt], aF[mt], &bF[nt >> 1][(nt & 1) << 1]);
        }
        __syncthreads();
    }

    const int g = lane >> 2, t4 = lane & 3;
    #pragma unroll
    for (int mt = 0; mt < 4; mt++) {
        const int rg0 = (tm << 7) + warpM * 64 + mt * 16 + g;
        const int rg1 = rg0 + 8;
        const bool a0 = rg0 < ce, a1 = rg1 < ce;
        const int n0 = a0 ? idxp[e * Nc + rg0] : 0;
        const int n1 = a1 ? idxp[e * Nc + rg1] : 0;
        #pragma unroll
        for (int nt = 0; nt < 4; nt++) {
            const int col = (tn << 7) + warpN * 32 + nt * 8 + (t4 << 1);
            if (a0)
                *(float2*)&C[((long long)n0 * Ec + e) * Cc + col] =
                    make_float2(acc[mt][nt][0], acc[mt][nt][1]);
            if (a1)
                *(float2*)&C[((long long)n1 * Ec + e) * Cc + col] =
                    make_float2(acc[mt][nt][2], acc[mt][nt][3]);
        }
    }
}

__global__ void zero_cnt_k(int* cnt) { if (threadIdx.x < Ec) cnt[threadIdx.x] = 0; }

__global__ void __launch_bounds__(256) zero_eo_k(float4* __restrict__ p, long long n4)
{
    long long i = (long long)blockIdx.x * 256 + threadIdx.x;
    const long long stride = (long long)gridDim.x * 256;
    for (; i < n4; i += stride) p[i] = make_float4(0.f, 0.f, 0.f, 0.f);
}

__global__ void __launch_bounds__(256) transpose_k(
    const float* __restrict__ in, float* __restrict__ out, int R, int C)
{
    __shared__ float t[32][33];
    const long long zo = (long long)blockIdx.z * R * C;
    const int c0 = blockIdx.x << 5, r0 = blockIdx.y << 5;
    const int tx = threadIdx.x & 31, ty = threadIdx.x >> 5;
    #pragma unroll
    for (int k = 0; k < 32; k += 8)
        t[ty + k][tx] = in[zo + (long long)(r0 + ty + k) * C + c0 + tx];
    __syncthreads();
    #pragma unroll
    for (int k = 0; k < 32; k += 8)
        out[zo + (long long)(c0 + ty + k) * R + r0 + tx] = t[tx][ty + k];
}

// ------- fp32 SGEMM, f32x2, BK=16 double-buffered (exact, order-preserving) -------
__device__ __forceinline__ void sgemm_core2(
    const float* __restrict__ A, const float* __restrict__ B,
    int K, int Np, int brow, int bcol, ull acc2[8][4])
{
    __shared__ __align__(16) float As[2][16][128];
    __shared__ __align__(16) float Bs[2][16][128];
    const int tid = threadIdx.x;
    const int ar = tid & 127, ac = (tid >> 7) << 3;
    const int bk = tid >> 4, bcl = (tid & 15) << 3;
    const int tx = tid & 15, ty = tid >> 4;
    const float* Arow = A + (long long)(brow + ar) * K + ac;
    const float* Bbase = B + bcol + bcl + (long long)bk * Np;

    #pragma unroll
    for (int i = 0; i < 8; i++)
        #pragma unroll
        for (int p = 0; p < 4; p++) acc2[i][p] = 0ull;

    float4 la0, la1, lb0, lb1;
    auto ldg = [&](int k0) {
        la0 = *(const float4*)(Arow + k0);
        la1 = *(const float4*)(Arow + k0 + 4);
        lb0 = *(const float4*)(Bbase + (long long)k0 * Np);
        lb1 = *(const float4*)(Bbase + (long long)k0 * Np + 4);
    };
    auto sts = [&](int s) {
        As[s][ac+0][ar] = la0.x; As[s][ac+1][ar] = la0.y;
        As[s][ac+2][ar] = la0.z; As[s][ac+3][ar] = la0.w;
        As[s][ac+4][ar] = la1.x; As[s][ac+5][ar] = la1.y;
        As[s][ac+6][ar] = la1.z; As[s][ac+7][ar] = la1.w;
        *(float4*)&Bs[s][bk][bcl] = lb0;
        *(float4*)&Bs[s][bk][bcl + 4] = lb1;
    };

    const int NC16 = K >> 4;
    ldg(0); sts(0);
    __syncthreads();
    for (int kc = 0; kc < NC16; kc++) {
        if (kc + 1 < NC16) ldg((kc + 1) << 4);
        const int s = kc & 1;
        #pragma unroll
        for (int kk = 0; kk < 16; kk++) {
            float4 a0 = *(const float4*)&As[s][kk][ty << 3];
            float4 a1 = *(const float4*)&As[s][kk][(ty << 3) + 4];
            ulonglong2 b01 = *(const ulonglong2*)&Bs[s][kk][tx << 3];
            ulonglong2 b23 = *(const ulonglong2*)&Bs[s][kk][(tx << 3) + 4];
            ull a2[8];
            a2[0]=dup2(a0.x); a2[1]=dup2(a0.y); a2[2]=dup2(a0.z); a2[3]=dup2(a0.w);
            a2[4]=dup2(a1.x); a2[5]=dup2(a1.y); a2[6]=dup2(a1.z); a2[7]=dup2(a1.w);
            #pragma unroll
            for (int i = 0; i < 8; i++) {
                fma2(acc2[i][0], a2[i], b01.x);
                fma2(acc2[i][1], a2[i], b01.y);
                fma2(acc2[i][2], a2[i], b23.x);
                fma2(acc2[i][3], a2[i], b23.y);
            }
        }
        if (kc + 1 < NC16) sts((kc + 1) & 1);
        __syncthreads();
    }
}

__global__ void __launch_bounds__(256, 2) gemm_res_k(
    const float* __restrict__ A, const float* __restrict__ B, float* __restrict__ C,
    const float* __restrict__ res)
{
    const int brow = blockIdx.y << 7, bcol = blockIdx.x << 7;
    ull acc2[8][4];
    sgemm_core2(A, B, Cc, Cc, brow, bcol, acc2);
    const int tx = threadIdx.x & 15, ty = threadIdx.x >> 4;
    #pragma unroll
    for (int i = 0; i < 8; i++) {
        const int row = brow + (ty << 3) + i;
        #pragma unroll
        for (int p = 0; p < 4; p += 2) {
            const int col = bcol + (tx << 3) + (p << 1);
            float2 e0 = unpk(acc2[i][p]), e1 = unpk(acc2[i][p + 1]);
            float4 v = make_float4(e0.x, e0.y, e1.x, e1.y);
            float4 rv = *(const float4*)&res[(long long)row * Cc + col];
            v.x += rv.x; v.y += rv.y; v.z += rv.z; v.w += rv.w;
            *(float4*)&C[(long long)row * Cc + col] = v;
        }
    }
}

// persistent QKV: 384 tiles stolen via global counter
__global__ void __launch_bounds__(256, 2) gemm_qkv_k(
    const float* __restrict__ A,
    const float* __restrict__ b0, const float* __restrict__ b1, const float* __restrict__ b2,
    float* __restrict__ c0, float* __restrict__ c1, float* __restrict__ c2,
    int* __restrict__ ctr)
{
    __shared__ __align__(16) int s_t;
    const int tid = threadIdx.x;
    const int tx = tid & 15, ty = tid >> 4;
    for (;;) {
        if (tid == 0) s_t = atomicAdd(ctr, 1);
        __syncthreads();
        const int t = s_t;
        __syncthreads();
        if (t >= 384) break;
        const int z = t >> 7, rem = t & 127;
        const float* B = (z == 0) ? b0 : (z == 1) ? b1 : b2;
        float* C = (z == 0) ? c0 : (z == 1) ? c1 : c2;
        const int brow = (rem >> 3) << 7, bcol = (rem & 7) << 7;
        ull acc2[8][4];
        sgemm_core2(A, B, Cc, Cc, brow, bcol, acc2);
        #pragma unroll
        for (int i = 0; i < 8; i++) {
            const int row = brow + (ty << 3) + i;
            #pragma unroll
            for (int p = 0; p < 4; p += 2) {
                const int col = bcol + (tx << 3) + (p << 1);
                float2 e0 = unpk(acc2[i][p]), e1 = unpk(acc2[i][p + 1]);
                *(float4*)&C[(long long)row * Cc + col] = make_float4(e0.x, e0.y, e1.x, e1.y);
            }
        }
    }
}

// ------- flash attention: 288 near-uniform blocks, exp2 phase softmax -------
#define AP 68
#define SM_ATTN2 (4 * 64 * AP * 4)
#define QSCALE 0.18033688011112042592f   /* 0.125 * log2(e) */
__global__ void __launch_bounds__(256) attn2_k(
    const float* __restrict__ Q, const float* __restrict__ K,
    const float* __restrict__ V, float* __restrict__ O)
{
    extern __shared__ float sm[];
    float* Qs = sm;
    float* Ks = sm + 64 * AP;
    float* Vs = sm + 2 * 64 * AP;
    float* Ps = sm + 3 * 64 * AP;
    const int bid = blockIdx.x;
    int combo, nseg, q0, q1;
    if (bid < 64) {
        combo = bid & 31; nseg = 1;
        q0 = 15 - (bid >> 5); q1 = 0;
    } else {
        const int pid = bid - 64;
        combo = pid & 31; nseg = 2;
        const int pi = pid >> 5;
        q0 = 13 - pi; q1 = pi;
    }
    const int h = combo & 15, b = combo >> 4;
    const int tid = threadIdx.x;
    const int tx = tid & 15, ty = tid >> 4;
    const long long base = ((long long)b * Tc) * Cc + h * Dc;
    const int lr = tid >> 4;
    const int lc = (tid & 15) << 2;

    for (int seg = 0; seg < nseg; seg++) {
        const int qt = seg ? q1 : q0;
        __syncthreads();
        #pragma unroll
        for (int rep = 0; rep < 4; rep++) {
            const int r = lr + (rep << 4);
            float4 v = *(const float4*)&Q[base + (long long)(qt * 64 + r) * Cc + lc];
            v.x *= QSCALE; v.y *= QSCALE; v.z *= QSCALE; v.w *= QSCALE;
            *(float4*)&Qs[r * AP + lc] = v;
        }

        ull acc2[4][2];
        float mi[4], li[4];
        #pragma unroll
        for (int i = 0; i < 4; i++) { acc2[i][0] = 0ull; acc2[i][1] = 0ull; mi[i] = -1e30f; li[i] = 0.f; }

        float4 kr[4], vr[4];
        #pragma unroll
        for (int rep = 0; rep < 4; rep++) {
            const int r = lr + (rep << 4);
            kr[rep] = *(const float4*)&K[base + (long long)r * Cc + lc];
            vr[rep] = *(const float4*)&V[base + (long long)r * Cc + lc];
        }

        for (int kt = 0; kt <= qt; kt++) {
            __syncthreads();
            #pragma unroll
            for (int rep = 0; rep < 4; rep++) {
                const int r = lr + (rep << 4);
                *(float4*)&Ks[r * AP + lc] = kr[rep];
                *(float4*)&Vs[r * AP + lc] = vr[rep];
            }
            __syncthreads();
            if (kt < qt) {
                #pragma unroll
                for (int rep = 0; rep < 4; rep++) {
                    const int r = lr + (rep << 4);
                    kr[rep] = *(const float4*)&K[base + (long long)((kt + 1) * 64 + r) * Cc + lc];
                    vr[rep] = *(const float4*)&V[base + (long long)((kt + 1) * 64 + r) * Cc + lc];
                }
            }
            ull s2[4][4];
            #pragma unroll
            for (int i = 0; i < 4; i++)
                #pragma unroll
                for (int j = 0; j < 4; j++) s2[i][j] = 0ull;
            #pragma unroll 4
            for (int d4 = 0; d4 < 16; d4++) {
                ulonglong2 la[4], lb[4];
                #pragma unroll
                for (int i = 0; i < 4; i++)
                    la[i] = *(const ulonglong2*)&Qs[((ty << 2) + i) * AP + (d4 << 2)];
                #pragma unroll
                for (int j = 0; j < 4; j++)
                    lb[j] = *(const ulonglong2*)&Ks[(tx + (j << 4)) * AP + (d4 << 2)];
                #pragma unroll
                for (int i = 0; i < 4; i++)
                    #pragma unroll
                    for (int j = 0; j < 4; j++) {
                        fma2(s2[i][j], la[i].x, lb[j].x);
                        fma2(s2[i][j], la[i].y, lb[j].y);
                    }
            }
            const bool diag = (kt == qt);
            float p[4][4], mloc[4];
            #pragma unroll
            for (int i = 0; i < 4; i++) {
                mloc[i] = -1e30f;
                #pragma unroll
                for (int j = 0; j < 4; j++) {
                    float2 u = unpk(s2[i][j]);
                    float sv = u.x + u.y;
                    if (diag && (tx + (j << 4)) > ((ty << 2) + i)) sv = -1e30f;
                    p[i][j] = sv;
                    mloc[i] = fmaxf(mloc[i], sv);
                }
            }
            #pragma unroll
            for (int st = 1; st <= 8; st <<= 1)
                #pragma unroll
                for (int i = 0; i < 4; i++)
                    mloc[i] = fmaxf(mloc[i], __shfl_xor_sync(0xffffffffu, mloc[i], st));
            float alpha[4], ps[4];
            #pragma unroll
            for (int i = 0; i < 4; i++) {
                const float mnew = fmaxf(mi[i], mloc[i]);
                alpha[i] = exp2f(mi[i] - mnew);
                mi[i] = mnew;
                ps[i] = 0.f;
                #pragma unroll
                for (int j = 0; j < 4; j++) {
                    p[i][j] = exp2f(p[i][j] - mnew);
                    ps[i] += p[i][j];
                }
            }
            #pragma unroll
            for (int st = 1; st <= 8; st <<= 1)
                #pragma unroll
                for (int i = 0; i < 4; i++)
                    ps[i] += __shfl_xor_sync(0xffffffffu, ps[i], st);
            #pragma unroll
            for (int i = 0; i < 4; i++) {
                li[i] = li[i] * alpha[i] + ps[i];
                const ull ad = dup2(alpha[i]);
                acc2[i][0] = mul2(acc2[i][0], ad);
                acc2[i][1] = mul2(acc2[i][1], ad);
                float* pr = &Ps[((ty << 2) + i) * AP + tx];
                pr[0] = p[i][0]; pr[16] = p[i][1]; pr[32] = p[i][2]; pr[48] = p[i][3];
            }
            __syncthreads();
            #pragma unroll 4
            for (int j4 = 0; j4 < 16; j4++) {
                float4 pa[4];
                #pragma unroll
                for (int i = 0; i < 4; i++)
                    pa[i] = *(const float4*)&Ps[((ty << 2) + i) * AP + (j4 << 2)];
                #pragma unroll
                for (int jj = 0; jj < 4; jj++) {
                    const ulonglong2 vb = *(const ulonglong2*)&Vs[((j4 << 2) + jj) * AP + (tx << 2)];
                    #pragma unroll
                    for (int i = 0; i < 4; i++) {
                        const float* pf = (const float*)&pa[i];
                        const ull pd = dup2(pf[jj]);
                        fma2(acc2[i][0], pd, vb.x);
                        fma2(acc2[i][1], pd, vb.y);
                    }
                }
            }
        }
        #pragma unroll
        for (int i = 0; i < 4; i++) {
            const float inv = 1.f / li[i];
            float2 e0 = unpk(acc2[i][0]), e1 = unpk(acc2[i][1]);
            float4 v = make_float4(e0.x * inv, e0.y * inv, e1.x * inv, e1.y * inv);
            *(float4*)&O[base + (long long)(qt * 64 + (ty << 2) + i) * Cc + (tx << 2)] = v;
        }
    }
}

__global__ void __launch_bounds__(256) ln_k(
    const float* __restrict__ x, const float* __restrict__ g,
    const float* __restrict__ b, float* __restrict__ o, int* __restrict__ ctr)
{
    const int n = blockIdx.x, tid = threadIdx.x;
    if (n == 0 && tid == 0) *ctr = 0;
    const long long rb = (long long)n << 10;
    const int c = tid << 2;
    float4 v = *(const float4*)&x[rb + c];
    float s = v.x + v.y + v.z + v.w;
    float ss = v.x*v.x + v.y*v.y + v.z*v.z + v.w*v.w;
    #pragma unroll
    for (int off = 16; off; off >>= 1) {
        s  += __shfl_xor_sync(0xffffffffu, s, off);
        ss += __shfl_xor_sync(0xffffffffu, ss, off);
    }
    __shared__ float rs[8], rss[8], mv[2];
    const int w = tid >> 5, lane = tid & 31;
    if (!lane) { rs[w] = s; rss[w] = ss; }
    __syncthreads();
    if (tid == 0) {
        float S = 0, SS = 0;
        #pragma unroll
        for (int i = 0; i < 8; i++) { S += rs[i]; SS += rss[i]; }
        const float mean = S * (1.f/1024.f);
        const float var = SS * (1.f/1024.f) - mean * mean;
        mv[0] = mean; mv[1] = rsqrtf(var + 1e-5f);
    }
    __syncthreads();
    const float mean = mv[0], rstd = mv[1];
    float4 gg = *(const float4*)&g[c], bb = *(const float4*)&b[c];
    float4 ov;
    ov.x = (v.x-mean)*rstd*gg.x + bb.x; ov.y = (v.y-mean)*rstd*gg.y + bb.y;
    ov.z = (v.z-mean)*rstd*gg.z + bb.z; ov.w = (v.w-mean)*rstd*gg.w + bb.w;
    *(float4*)&o[rb + c] = ov;
}

__global__ void __launch_bounds__(256) colnorm_k(
    const float* __restrict__ sim, float* __restrict__ colinv)
{
    const int e = blockIdx.x, tid = threadIdx.x;
    float s = 0.f;
    for (int cc = tid; cc < 1024; cc += 256) {
        const float v = sim[cc * 16 + e];
        s = fmaf(v, v, s);
    }
    #pragma unroll
    for (int off = 16; off; off >>= 1) s += __shfl_xor_sync(0xffffffffu, s, off);
    __shared__ float rs[8];
    const int w = tid >> 5, lane = tid & 31;
    if (!lane) rs[w] = s;
    __syncthreads();
    if (tid == 0) {
        float S = 0;
        #pragma unroll
        for (int i = 0; i < 8; i++) S += rs[i];
        colinv[e] = rsqrtf(S);
    }
}

__global__ void __launch_bounds__(256) lnscore_k(
    const float* __restrict__ x1, const float* __restrict__ g, const float* __restrict__ b,
    const float* __restrict__ sim, const float* __restrict__ thr,
    const float* __restrict__ colinv, float* __restrict__ oh2,
    float* __restrict__ oscores, float* __restrict__ okpt, float* __restrict__ maskb,
    int* __restrict__ cnt, int* __restrict__ idxp)
{
    const int n = blockIdx.x, tid = threadIdx.x;
    const long long rb = (long long)n << 10;
    const int c = tid << 2;
    const int w = tid >> 5, lane = tid & 31;

    float4 xv = *(const float4*)&x1[rb + c];
    {
        float s  = xv.x + xv.y + xv.z + xv.w;
        float ss = xv.x*xv.x + xv.y*xv.y + xv.z*xv.z + xv.w*xv.w;
        #pragma unroll
        for (int off = 16; off; off >>= 1) {
            s  += __shfl_xor_sync(0xffffffffu, s, off);
            ss += __shfl_xor_sync(0xffffffffu, ss, off);
        }
        __shared__ float rs0[8], rss0[8], mv[2];
        if (!lane) { rs0[w] = s; rss0[w] = ss; }
        __syncthreads();
        if (tid == 0) {
            float S = 0, SS = 0;
            #pragma unroll
            for (int i = 0; i < 8; i++) { S += rs0[i]; SS += rss0[i]; }
            const float mean = S * (1.f/1024.f);
            const float var = SS * (1.f/1024.f) - mean * mean;
            mv[0] = mean; mv[1] = rsqrtf(var + 1e-5f);
        }
        __syncthreads();
        const float mean = mv[0], rstd = mv[1];
        float4 gg = *(const float4*)&g[c], bb = *(const float4*)&b[c];
        xv.x = (xv.x-mean)*rstd*gg.x + bb.x; xv.y = (xv.y-mean)*rstd*gg.y + bb.y;
        xv.z = (xv.z-mean)*rstd*gg.z + bb.z; xv.w = (xv.w-mean)*rstd*gg.w + bb.w;
        *(float4*)&oh2[rb + c] = xv;
    }
    __syncthreads();

    float ss = xv.x*xv.x + xv.y*xv.y + xv.z*xv.z + xv.w*xv.w;
    float accd[16];
    #pragma unroll
    for (int e = 0; e < 16; e++) accd[e] = 0.f;
    const float hv[4] = {xv.x, xv.y, xv.z, xv.w};
    #pragma unroll
    for (int cc = 0; cc < 4; cc++) {
        const float* sr = &sim[(long long)(c + cc) << 4];
        #pragma unroll
        for (int e = 0; e < 16; e++) accd[e] = fmaf(hv[cc], sr[e], accd[e]);
    }
    #pragma unroll
    for (int off = 16; off; off >>= 1) ss += __shfl_xor_sync(0xffffffffu, ss, off);
    __shared__ float rs[8];
    __shared__ float red[16 * 8];
    __shared__ float smask[16];
    __shared__ float srn;
    if (!lane) rs[w] = ss;
    #pragma unroll
    for (int e = 0; e < 16; e++) {
        float t = accd[e];
        #pragma unroll
        for (int off = 16; off; off >>= 1) t += __shfl_xor_sync(0xffffffffu, t, off);
        if (!lane) red[e * 8 + w] = t;
    }
    __syncthreads();
    if (tid == 0) {
        float S = 0;
        #pragma unroll
        for (int i = 0; i < 8; i++) S += rs[i];
        srn = rsqrtf(S);
    }
    __syncthreads();
    if (tid < 16) {
        float sum = 0;
        #pragma unroll
        for (int i = 0; i < 8; i++) sum += red[tid * 8 + i];
        const float sc = sum * srn * colinv[tid];
        oscores[(n << 4) + tid] = sc;
        const float m = (sc > thr[0]) ? 1.f : 0.f;
        maskb[(n << 4) + tid] = m;
        smask[tid] = m;
        if (m != 0.f) {
            const int pos = atomicAdd(&cnt[tid], 1);
            idxp[tid * Nc + pos] = n;
        }
    }
    __syncthreads();
    if (tid == 0) {
        float kc = 0;
        #pragma unroll
        for (int e = 0; e < 16; e++) kc += smask[e];
        okpt[n] = kc;
    }
}

__global__ void __launch_bounds__(256) final_k(
    const float* __restrict__ x1, const float* __restrict__ eo,
    const float* __restrict__ maskb, float* __restrict__ ox)
{
    const int n = blockIdx.x, tid = threadIdx.x;
    __shared__ float mk[16];
    if (tid < 16) mk[tid] = maskb[(n << 4) + tid];
    __syncthreads();
    const int c = tid << 2;
    const long long rb = (long long)n << 10;
    float4 v = *(const float4*)&x1[rb + c];
    #pragma unroll
    for (int e = 0; e < 16; e++) {
        if (mk[e] != 0.f) {
            const float4 wv = *(const float4*)&eo[(((long long)(n * 16 + e)) << 10) + c];
            v.x += wv.x; v.y += wv.y; v.z += wv.z; v.w += wv.w;
        }
    }
    *(float4*)&ox[rb + c] = v;
}

extern "C" void kernel_launch(void* const* d_in, const int* in_sizes, int n_in,
                              void* d_out, int out_size)
{
    (void)in_sizes; (void)n_in;
    const float* x    = (const float*)d_in[0];
    const float* ln1g = (const float*)d_in[1];
    const float* ln1b = (const float*)d_in[2];
    const float* ln2g = (const float*)d_in[3];
    const float* ln2b = (const float*)d_in[4];
    const float* wq   = (const float*)d_in[5];
    const float* wk   = (const float*)d_in[6];
    const float* wv   = (const float*)d_in[7];
    const float* wo   = (const float*)d_in[8];
    const float* sim  = (const float*)d_in[9];
    const float* thr  = (const float*)d_in[10];
    const float* w1   = (const float*)d_in[11];
    const float* w2   = (const float*)d_in[12];

    float *ph, *pq, *pk, *pv, *pao, *px1, *pmid, *pw1t, *pw2t, *peos, *pmask, *pcol, *pssc, *pkpt;
    int *pcnt, *pidx, *pctr;
    cudaGetSymbolAddress((void**)&ph, g_h);
    cudaGetSymbolAddress((void**)&pq, g_q);
    cudaGetSymbolAddress((void**)&pk, g_k);
    cudaGetSymbolAddress((void**)&pv, g_v);
    cudaGetSymbolAddress((void**)&pao, g_ao);
    cudaGetSymbolAddress((void**)&px1, g_x1);
    cudaGetSymbolAddress((void**)&pmid, g_mid);
    cudaGetSymbolAddress((void**)&pw1t, g_w1t);
    cudaGetSymbolAddress((void**)&pw2t, g_w2t);
    cudaGetSymbolAddress((void**)&peos, g_eo_scr);
    cudaGetSymbolAddress((void**)&pmask, g_mask);
    cudaGetSymbolAddress((void**)&pcol, g_colinv);
    cudaGetSymbolAddress((void**)&pssc, g_scores_scr);
    cudaGetSymbolAddress((void**)&pkpt, g_kpt_scr);
    cudaGetSymbolAddress((void**)&pcnt, g_cnt);
    cudaGetSymbolAddress((void**)&pidx, g_idx);
    cudaGetSymbolAddress((void**)&pctr, g_qkv_ctr);

    const long long XN  = (long long)Nc * Cc;
    const long long SCN = (long long)Nc * Ec;
    const long long EON = (long long)Nc * Ec * Cc;
    const bool full = ((long long)out_size >= XN + SCN + EON + Nc);
    float* out   = (float*)d_out;
    float* o_x   = out;
    float* o_sc  = full ? out + XN : pssc;
    float* o_eo  = full ? out + XN + SCN : peos;
    float* o_kpt = full ? out + XN + SCN + EON : pkpt;

    cudaFuncSetAttribute(attn2_k, cudaFuncAttributeMaxDynamicSharedMemorySize, SM_ATTN2);
    cudaFuncSetAttribute(moe_g1_k, cudaFuncAttributeMaxDynamicSharedMemorySize, MOE_SMEM);
    cudaFuncSetAttribute(moe_s2_k, cudaFuncAttributeMaxDynamicSharedMemorySize, MOE_SMEM);

    // ---- side stream: independent prep (hidden under main chain) ----
    cudaStream_t s2;
    cudaStreamCreateWithFlags(&s2, cudaStreamNonBlocking);
    cudaEvent_t ev1, evPrep;
    cudaEventCreateWithFlags(&ev1, cudaEventDisableTiming);
    cudaEventCreateWithFlags(&evPrep, cudaEventDisableTiming);
    cudaEventRecord(ev1, 0);
    cudaStreamWaitEvent(s2, ev1, 0);
    zero_eo_k<<<2048, 256, 0, s2>>>((float4*)o_eo, EON / 4);
    zero_cnt_k<<<1, 32, 0, s2>>>(pcnt);
    transpose_k<<<dim3(8, 32, 16), 256, 0, s2>>>(w1, pw1t, Cc, Ic);
    transpose_k<<<dim3(32, 8, 16), 256, 0, s2>>>(w2, pw2t, Ic, Cc);
    colnorm_k<<<16, 256, 0, s2>>>(sim, pcol);
    cudaEventRecord(evPrep, s2);

    // ---- main chain ----
    ln_k<<<Nc, 256>>>(x, ln1g, ln1b, ph, pctr);
    gemm_qkv_k<<<296, 256>>>(ph, wq, wk, wv, pq, pk, pv, pctr);
    attn2_k<<<288, 256, SM_ATTN2>>>(pq, pk, pv, pao);
    gemm_res_k<<<dim3(8, 16, 1), 256>>>(pao, wo, px1, x);

    cudaStreamWaitEvent(0, evPrep, 0);
    lnscore_k<<<Nc, 256>>>(px1, ln2g, ln2b, sim, thr, pcol, ph,
                           o_sc, o_kpt, pmask, pcnt, pidx);

    moe_g1_k<<<dim3(2, 16, Ec), 256, MOE_SMEM>>>(ph, pw1t, pmid, pidx, pcnt);
    moe_s2_k<<<dim3(8, 16, Ec), 256, MOE_SMEM>>>(pmid, pw2t, o_eo, pidx, pcnt);

    final_k<<<Nc, 256>>>(px1, o_eo, pmask, o_x);
}